// round 1
// baseline (speedup 1.0000x reference)
#include <cuda_runtime.h>

// Problem constants
#define BATCH 2
#define SEQ   2048
#define EMB   1024
#define NH    16
#define HD    64
#define MTOT  (BATCH * SEQ)     // 4096
#define NQKV  (3 * EMB)         // 3072

// Scratch (device globals: allocation-free rule)
__device__ float g_qkv[(size_t)MTOT * NQKV];   // [4096, 3072]
__device__ float g_attn[(size_t)MTOT * EMB];   // [4096, 1024]

// ---------------------------------------------------------------------------
// Tiled SGEMM with bias:  C[M,N] = A[M,K] @ W[N,K]^T + bias[N]
// 128x128x32 tiles, 256 threads, 8x8 per thread (split 2x2 of 4x4 fragments)
// ---------------------------------------------------------------------------
#define TBM 128
#define TBN 128
#define TBK 32
#define LDS_GEMM 132   // TBM + 4 pad: float4-aligned (132*4 % 16 == 0), low conflicts

__global__ __launch_bounds__(256, 2)
void gemm_bias(const float* __restrict__ A, const float* __restrict__ W,
               const float* __restrict__ bias, float* __restrict__ C,
               int M, int N, int K)
{
    __shared__ __align__(16) float As[TBK * LDS_GEMM];
    __shared__ __align__(16) float Bs[TBK * LDS_GEMM];

    const int tid = threadIdx.x;
    const int tr  = tid >> 4;    // 0..15
    const int tc  = tid & 15;    // 0..15
    const int m0  = blockIdx.y * TBM;
    const int n0  = blockIdx.x * TBN;

    const float* Ab = A + (size_t)m0 * K;
    const float* Wb = W + (size_t)n0 * K;

    float acc[8][8];
#pragma unroll
    for (int i = 0; i < 8; i++)
#pragma unroll
        for (int j = 0; j < 8; j++) acc[i][j] = 0.0f;

    for (int kt = 0; kt < K; kt += TBK) {
        // Load A tile [128 x 32] and W tile [128 x 32], store k-major
#pragma unroll
        for (int it = 0; it < 4; it++) {
            int idx = tid + it * 256;          // 0..1023 float4 slots
            int row = idx >> 3;                // 0..127
            int c4  = (idx & 7) << 2;          // 0,4,...,28
            float4 va = *(const float4*)(Ab + (size_t)row * K + kt + c4);
            As[(c4 + 0) * LDS_GEMM + row] = va.x;
            As[(c4 + 1) * LDS_GEMM + row] = va.y;
            As[(c4 + 2) * LDS_GEMM + row] = va.z;
            As[(c4 + 3) * LDS_GEMM + row] = va.w;
            float4 vb = *(const float4*)(Wb + (size_t)row * K + kt + c4);
            Bs[(c4 + 0) * LDS_GEMM + row] = vb.x;
            Bs[(c4 + 1) * LDS_GEMM + row] = vb.y;
            Bs[(c4 + 2) * LDS_GEMM + row] = vb.z;
            Bs[(c4 + 3) * LDS_GEMM + row] = vb.w;
        }
        __syncthreads();

#pragma unroll 8
        for (int k = 0; k < TBK; k++) {
            float a[8], b[8];
            float4 t;
            t = *(const float4*)&As[k * LDS_GEMM + tr * 4];
            a[0] = t.x; a[1] = t.y; a[2] = t.z; a[3] = t.w;
            t = *(const float4*)&As[k * LDS_GEMM + 64 + tr * 4];
            a[4] = t.x; a[5] = t.y; a[6] = t.z; a[7] = t.w;
            t = *(const float4*)&Bs[k * LDS_GEMM + tc * 4];
            b[0] = t.x; b[1] = t.y; b[2] = t.z; b[3] = t.w;
            t = *(const float4*)&Bs[k * LDS_GEMM + 64 + tc * 4];
            b[4] = t.x; b[5] = t.y; b[6] = t.z; b[7] = t.w;
#pragma unroll
            for (int i = 0; i < 8; i++)
#pragma unroll
                for (int j = 0; j < 8; j++)
                    acc[i][j] = fmaf(a[i], b[j], acc[i][j]);
        }
        __syncthreads();
    }

    // Epilogue with bias
#pragma unroll
    for (int ab = 0; ab < 2; ab++) {
#pragma unroll
        for (int i = 0; i < 4; i++) {
            int r = m0 + ab * 64 + tr * 4 + i;
            float* Crow = C + (size_t)r * N + n0;
#pragma unroll
            for (int bb = 0; bb < 2; bb++) {
                int c = bb * 64 + tc * 4;
                float4 bi = *(const float4*)(bias + n0 + c);
                float4 o;
                o.x = acc[ab * 4 + i][bb * 4 + 0] + bi.x;
                o.y = acc[ab * 4 + i][bb * 4 + 1] + bi.y;
                o.z = acc[ab * 4 + i][bb * 4 + 2] + bi.z;
                o.w = acc[ab * 4 + i][bb * 4 + 3] + bi.w;
                *(float4*)(Crow + c) = o;
            }
        }
    }
}

// ---------------------------------------------------------------------------
// Flash attention (fp32, online softmax), causal-aware tile skipping.
// Grid: (SEQ/64, BATCH*NH), 256 threads. Q/K tiles stored k-major with XOR
// swizzle (stride 64), V row-major; P reuses the K buffer.
// Exactly 48KB static smem: 3 * 64*64*4 = 49152 bytes.
// ---------------------------------------------------------------------------
__global__ __launch_bounds__(256)
void attention_kernel(const float* __restrict__ qkv, float* __restrict__ attn,
                      const int* __restrict__ causal_flag)
{
    __shared__ __align__(16) float qs[64 * 64];  // Q^T swizzled: [k][row]
    __shared__ __align__(16) float ks[64 * 64];  // K^T swizzled: [k][col]; reused as P^T [kv][q]
    __shared__ __align__(16) float vs[64 * 64];  // V: [kv][d]

    const int tid = threadIdx.x;
    const int tr  = tid >> 4;    // 0..15 -> q rows tr*4..
    const int tc  = tid & 15;    // 0..15 -> cols tc*4..
    const int qt  = blockIdx.x;
    const int bh  = blockIdx.y;
    const int b   = bh / NH;
    const int h   = bh % NH;
    const int causal = *causal_flag;
    const int q0  = qt * 64;

    const size_t base = (size_t)(b * SEQ) * NQKV + h * HD;
    const float* Qg = qkv + base + (size_t)q0 * NQKV;  // row stride NQKV, 64 cols
    const float* Kg = qkv + base + EMB;
    const float* Vg = qkv + base + 2 * EMB;

    // Load Q tile (64x64), transpose + swizzle into qs[k*64 + (row ^ (k&31))]
#pragma unroll
    for (int it = 0; it < 4; it++) {
        int idx = tid + it * 256;
        int row = idx >> 4;              // 0..63
        int c4  = (idx & 15) << 2;       // 0,4,...,60
        float4 v = *(const float4*)(Qg + (size_t)row * NQKV + c4);
        qs[(c4 + 0) * 64 + (row ^ ((c4 + 0) & 31))] = v.x;
        qs[(c4 + 1) * 64 + (row ^ ((c4 + 1) & 31))] = v.y;
        qs[(c4 + 2) * 64 + (row ^ ((c4 + 2) & 31))] = v.z;
        qs[(c4 + 3) * 64 + (row ^ ((c4 + 3) & 31))] = v.w;
    }

    float o[4][4];
    float m[4], l[4];
#pragma unroll
    for (int i = 0; i < 4; i++) {
        m[i] = -1e30f; l[i] = 0.0f;
#pragma unroll
        for (int j = 0; j < 4; j++) o[i][j] = 0.0f;
    }

    const int nkv = causal ? (qt + 1) : (SEQ / 64);
    for (int kvt = 0; kvt < nkv; kvt++) {
        const int kv0 = kvt * 64;

        // Load K (transpose+swizzle) and V (row-major) tiles
#pragma unroll
        for (int it = 0; it < 4; it++) {
            int idx = tid + it * 256;
            int row = idx >> 4;
            int c4  = (idx & 15) << 2;
            float4 kv4 = *(const float4*)(Kg + (size_t)(kv0 + row) * NQKV + c4);
            ks[(c4 + 0) * 64 + (row ^ ((c4 + 0) & 31))] = kv4.x;
            ks[(c4 + 1) * 64 + (row ^ ((c4 + 1) & 31))] = kv4.y;
            ks[(c4 + 2) * 64 + (row ^ ((c4 + 2) & 31))] = kv4.z;
            ks[(c4 + 3) * 64 + (row ^ ((c4 + 3) & 31))] = kv4.w;
            float4 vv = *(const float4*)(Vg + (size_t)(kv0 + row) * NQKV + c4);
            *(float4*)&vs[row * 64 + c4] = vv;
        }
        __syncthreads();

        // S = Q @ K^T  (4x4 per thread)
        float s[4][4];
#pragma unroll
        for (int i = 0; i < 4; i++)
#pragma unroll
            for (int j = 0; j < 4; j++) s[i][j] = 0.0f;

#pragma unroll 4
        for (int k = 0; k < 64; k++) {
            const int sw = k & 31;
            float a0 = qs[k * 64 + ((tr * 4 + 0) ^ sw)];
            float a1 = qs[k * 64 + ((tr * 4 + 1) ^ sw)];
            float a2 = qs[k * 64 + ((tr * 4 + 2) ^ sw)];
            float a3 = qs[k * 64 + ((tr * 4 + 3) ^ sw)];
            float b0 = ks[k * 64 + ((tc * 4 + 0) ^ sw)];
            float b1 = ks[k * 64 + ((tc * 4 + 1) ^ sw)];
            float b2 = ks[k * 64 + ((tc * 4 + 2) ^ sw)];
            float b3 = ks[k * 64 + ((tc * 4 + 3) ^ sw)];
            s[0][0] = fmaf(a0, b0, s[0][0]); s[0][1] = fmaf(a0, b1, s[0][1]);
            s[0][2] = fmaf(a0, b2, s[0][2]); s[0][3] = fmaf(a0, b3, s[0][3]);
            s[1][0] = fmaf(a1, b0, s[1][0]); s[1][1] = fmaf(a1, b1, s[1][1]);
            s[1][2] = fmaf(a1, b2, s[1][2]); s[1][3] = fmaf(a1, b3, s[1][3]);
            s[2][0] = fmaf(a2, b0, s[2][0]); s[2][1] = fmaf(a2, b1, s[2][1]);
            s[2][2] = fmaf(a2, b2, s[2][2]); s[2][3] = fmaf(a2, b3, s[2][3]);
            s[3][0] = fmaf(a3, b0, s[3][0]); s[3][1] = fmaf(a3, b1, s[3][1]);
            s[3][2] = fmaf(a3, b2, s[3][2]); s[3][3] = fmaf(a3, b3, s[3][3]);
        }

        // Scale + causal mask (only possible on the diagonal tile)
        const float scl = 0.125f;   // 1/sqrt(64)
        const bool domask = (causal != 0) && (kvt == qt);
#pragma unroll
        for (int i = 0; i < 4; i++) {
            int qrow = tr * 4 + i;
#pragma unroll
            for (int j = 0; j < 4; j++) {
                float v = s[i][j] * scl;
                if (domask && (tc * 4 + j > qrow)) v = -1e30f;
                s[i][j] = v;
            }
        }

        __syncthreads();   // everyone done reading ks (about to overwrite with P^T)

        // Online softmax update + store P^T into ks
#pragma unroll
        for (int i = 0; i < 4; i++) {
            float tm = fmaxf(fmaxf(s[i][0], s[i][1]), fmaxf(s[i][2], s[i][3]));
#pragma unroll
            for (int off = 8; off >= 1; off >>= 1)
                tm = fmaxf(tm, __shfl_xor_sync(0xffffffffu, tm, off));
            float mn = fmaxf(m[i], tm);
            float alpha = __expf(m[i] - mn);
            m[i] = mn;
            float rs = 0.0f;
#pragma unroll
            for (int j = 0; j < 4; j++) {
                float p = __expf(s[i][j] - mn);
                s[i][j] = p;
                rs += p;
            }
#pragma unroll
            for (int off = 8; off >= 1; off >>= 1)
                rs += __shfl_xor_sync(0xffffffffu, rs, off);
            l[i] = l[i] * alpha + rs;
#pragma unroll
            for (int j = 0; j < 4; j++) o[i][j] *= alpha;
            // P^T[kv][q] swizzled
#pragma unroll
            for (int j = 0; j < 4; j++) {
                int kv = tc * 4 + j;
                ks[kv * 64 + ((tr * 4 + i) ^ (kv & 31))] = s[i][j];
            }
        }
        __syncthreads();

        // O += P @ V
#pragma unroll 4
        for (int kv = 0; kv < 64; kv++) {
            float4 bv = *(const float4*)&vs[kv * 64 + tc * 4];
            const int sw = kv & 31;
#pragma unroll
            for (int i = 0; i < 4; i++) {
                float a = ks[kv * 64 + ((tr * 4 + i) ^ sw)];
                o[i][0] = fmaf(a, bv.x, o[i][0]);
                o[i][1] = fmaf(a, bv.y, o[i][1]);
                o[i][2] = fmaf(a, bv.z, o[i][2]);
                o[i][3] = fmaf(a, bv.w, o[i][3]);
            }
        }
        __syncthreads();   // done with ks/vs before next tile's loads
    }

    // Normalize and write to (b, s, h*64 + d) layout
#pragma unroll
    for (int i = 0; i < 4; i++) {
        float inv = 1.0f / l[i];
        size_t r = (size_t)(b * SEQ + q0 + tr * 4 + i);
        float4 ov;
        ov.x = o[i][0] * inv; ov.y = o[i][1] * inv;
        ov.z = o[i][2] * inv; ov.w = o[i][3] * inv;
        *(float4*)&attn[r * EMB + h * HD + tc * 4] = ov;
    }
}

// ---------------------------------------------------------------------------
extern "C" void kernel_launch(void* const* d_in, const int* in_sizes, int n_in,
                              void* d_out, int out_size)
{
    (void)in_sizes; (void)n_in; (void)out_size;
    const float* x      = (const float*)d_in[0];
    const float* w_qkv  = (const float*)d_in[1];
    const float* b_qkv  = (const float*)d_in[2];
    const float* w_out  = (const float*)d_in[3];
    const float* b_out  = (const float*)d_in[4];
    const int*   causal = (const int*)d_in[5];
    float* out = (float*)d_out;

    float *qkvbuf = nullptr, *attnbuf = nullptr;
    cudaGetSymbolAddress((void**)&qkvbuf, g_qkv);
    cudaGetSymbolAddress((void**)&attnbuf, g_attn);

    dim3 blk(256);
    // QKV projection: [4096,1024] @ [3072,1024]^T -> [4096,3072]
    gemm_bias<<<dim3(NQKV / TBN, MTOT / TBM), blk>>>(x, w_qkv, b_qkv, qkvbuf,
                                                     MTOT, NQKV, EMB);
    // Causal flash attention -> [4096,1024] in (b,s,e) layout
    attention_kernel<<<dim3(SEQ / 64, BATCH * NH), blk>>>(qkvbuf, attnbuf, causal);
    // Output projection: [4096,1024] @ [1024,1024]^T -> [4096,1024]
    gemm_bias<<<dim3(EMB / TBN, MTOT / TBM), blk>>>(attnbuf, w_out, b_out, out,
                                                    MTOT, EMB, EMB);
}

// round 4
// speedup vs baseline: 2.8034x; 2.8034x over previous
#include <cuda_runtime.h>
#include <cuda_bf16.h>
#include <cstdint>

// Problem constants
#define BATCH 2
#define SEQ   2048
#define EMB   1024
#define NH    16
#define HD    64
#define MTOT  (BATCH * SEQ)     // 4096
#define NQKV  (3 * EMB)         // 3072

// Scratch (device globals: allocation-free rule)
__device__ float g_qkv[(size_t)MTOT * NQKV];   // [4096, 3072]
__device__ float g_attn[(size_t)MTOT * EMB];   // [4096, 1024]

// ---------------------------------------------------------------------------
// bf16 split helpers
// ---------------------------------------------------------------------------
__device__ __forceinline__ uint32_t f2bfbits(float x) {
    __nv_bfloat16 b = __float2bfloat16(x);
    return (uint32_t)*reinterpret_cast<unsigned short*>(&b);
}
__device__ __forceinline__ float bfbits2f(uint32_t b16) {
    return __uint_as_float(b16 << 16);
}
__device__ __forceinline__ uint32_t packbf(float x, float y) {
    return f2bfbits(x) | (f2bfbits(y) << 16);
}
// x,y -> (hi pair, lo pair) with x in low half
__device__ __forceinline__ void packsplit(float x, float y,
                                          uint32_t& hi, uint32_t& lo) {
    hi = packbf(x, y);
    lo = packbf(x - bfbits2f(hi & 0xffffu), y - bfbits2f(hi >> 16));
}

// mma.sync m16n8k16 bf16 (A row-major, B col-major), D += A*B
__device__ __forceinline__ void mma16816(float* d, const uint32_t* a,
                                         const uint32_t* b) {
    asm volatile(
        "mma.sync.aligned.m16n8k16.row.col.f32.bf16.bf16.f32 "
        "{%0,%1,%2,%3}, {%4,%5,%6,%7}, {%8,%9}, {%0,%1,%2,%3};"
        : "+f"(d[0]), "+f"(d[1]), "+f"(d[2]), "+f"(d[3])
        : "r"(a[0]), "r"(a[1]), "r"(a[2]), "r"(a[3]), "r"(b[0]), "r"(b[1]));
}

// ---------------------------------------------------------------------------
// GEMM via mma.sync, 3-term bf16 split: C[M,N] = A[M,K] @ W[N,K]^T + bias[N]
// CTA 128x128, BK=32, 8 warps (2m x 4n), warp tile 64x32.
// smem rows: 32 bf16 = 64B + 16B pad = 80B stride (conflict-free frag LDS).
// ---------------------------------------------------------------------------
#define GBM 128
#define GBN 128
#define GBK 32
#define GSTRIDE 80
#define GP_A_HI 0u
#define GP_A_LO 10240u
#define GP_B_HI 20480u
#define GP_B_LO 30720u
#define GSTAGE  40960u
#define GEMM_SMEM (2u * GSTAGE)   // 81920 bytes

__global__ __launch_bounds__(256)
void gemm_mma(const float* __restrict__ A, const float* __restrict__ W,
              const float* __restrict__ bias, float* __restrict__ C,
              int M, int N, int K)
{
    extern __shared__ __align__(16) char sm[];
    const int tid  = threadIdx.x;
    const int wid  = tid >> 5, lane = tid & 31;
    const int g    = lane >> 2, tg = lane & 3;
    const int m0   = blockIdx.y * GBM, n0 = blockIdx.x * GBN;
    const int m0w  = (wid >> 2) * 64, n0w = (wid & 3) * 32;

    const float* Ab = A + (size_t)m0 * K;
    const float* Wb = W + (size_t)n0 * K;

    float acc[4][4][4];
#pragma unroll
    for (int i = 0; i < 4; i++)
#pragma unroll
        for (int j = 0; j < 4; j++)
#pragma unroll
            for (int e = 0; e < 4; e++) acc[i][j][e] = 0.0f;

    float4 abuf[4], bbuf[4];

    auto ldg = [&](int kt) {
#pragma unroll
        for (int it = 0; it < 4; it++) {
            int idx = tid + it * 256;
            int row = idx >> 3, c4 = (idx & 7) << 2;
            abuf[it] = *(const float4*)(Ab + (size_t)row * K + kt + c4);
            bbuf[it] = *(const float4*)(Wb + (size_t)row * K + kt + c4);
        }
    };
    auto sts = [&](uint32_t so) {
#pragma unroll
        for (int it = 0; it < 4; it++) {
            int idx = tid + it * 256;
            int row = idx >> 3, c8 = (idx & 7) << 3;   // byte col offset
            uint32_t off = so + (uint32_t)(row * GSTRIDE + c8);
            uint32_t h0, l0, h1, l1;
            packsplit(abuf[it].x, abuf[it].y, h0, l0);
            packsplit(abuf[it].z, abuf[it].w, h1, l1);
            *(uint2*)(sm + GP_A_HI + off) = make_uint2(h0, h1);
            *(uint2*)(sm + GP_A_LO + off) = make_uint2(l0, l1);
            packsplit(bbuf[it].x, bbuf[it].y, h0, l0);
            packsplit(bbuf[it].z, bbuf[it].w, h1, l1);
            *(uint2*)(sm + GP_B_HI + off) = make_uint2(h0, h1);
            *(uint2*)(sm + GP_B_LO + off) = make_uint2(l0, l1);
        }
    };
    auto compute = [&](uint32_t so) {
#pragma unroll
        for (int ks = 0; ks < 2; ks++) {
            const uint32_t kb = (uint32_t)(ks * 32 + tg * 4);
            uint32_t aH[4][4], aL[4][4], bH[4][2], bL[4][2];
#pragma unroll
            for (int mf = 0; mf < 4; mf++) {
                uint32_t ab = so + (uint32_t)((m0w + mf * 16 + g) * GSTRIDE) + kb;
                aH[mf][0] = *(const uint32_t*)(sm + GP_A_HI + ab);
                aH[mf][1] = *(const uint32_t*)(sm + GP_A_HI + ab + 8 * GSTRIDE);
                aH[mf][2] = *(const uint32_t*)(sm + GP_A_HI + ab + 16);
                aH[mf][3] = *(const uint32_t*)(sm + GP_A_HI + ab + 8 * GSTRIDE + 16);
                aL[mf][0] = *(const uint32_t*)(sm + GP_A_LO + ab);
                aL[mf][1] = *(const uint32_t*)(sm + GP_A_LO + ab + 8 * GSTRIDE);
                aL[mf][2] = *(const uint32_t*)(sm + GP_A_LO + ab + 16);
                aL[mf][3] = *(const uint32_t*)(sm + GP_A_LO + ab + 8 * GSTRIDE + 16);
            }
#pragma unroll
            for (int nf = 0; nf < 4; nf++) {
                uint32_t bb = so + (uint32_t)((n0w + nf * 8 + g) * GSTRIDE) + kb;
                bH[nf][0] = *(const uint32_t*)(sm + GP_B_HI + bb);
                bH[nf][1] = *(const uint32_t*)(sm + GP_B_HI + bb + 16);
                bL[nf][0] = *(const uint32_t*)(sm + GP_B_LO + bb);
                bL[nf][1] = *(const uint32_t*)(sm + GP_B_LO + bb + 16);
            }
#pragma unroll
            for (int mf = 0; mf < 4; mf++)
#pragma unroll
                for (int nf = 0; nf < 4; nf++) {
                    mma16816(acc[mf][nf], aH[mf], bH[nf]);
                    mma16816(acc[mf][nf], aH[mf], bL[nf]);
                    mma16816(acc[mf][nf], aL[mf], bH[nf]);
                }
        }
    };

    ldg(0);
    sts(0);
    __syncthreads();

    const int NC = K / GBK;
    for (int c = 0; c < NC; c++) {
        uint32_t so = (uint32_t)(c & 1) * GSTAGE;
        if (c + 1 < NC) ldg((c + 1) * GBK);     // overlap LDG with mma
        compute(so);
        if (c + 1 < NC) sts((uint32_t)((c + 1) & 1) * GSTAGE);
        __syncthreads();
    }

    // epilogue: D frag c0,c1 = (row, col..col+1); c2,c3 = (row+8, ...)
#pragma unroll
    for (int mf = 0; mf < 4; mf++) {
        int r = m0 + m0w + mf * 16 + g;
#pragma unroll
        for (int nf = 0; nf < 4; nf++) {
            int col = n0 + n0w + nf * 8 + tg * 2;
            float b0 = bias[col], b1 = bias[col + 1];
            *(float2*)(C + (size_t)r * N + col) =
                make_float2(acc[mf][nf][0] + b0, acc[mf][nf][1] + b1);
            *(float2*)(C + (size_t)(r + 8) * N + col) =
                make_float2(acc[mf][nf][2] + b0, acc[mf][nf][3] + b1);
        }
    }
}

// ---------------------------------------------------------------------------
// Flash attention with mma.sync (3-term bf16 splits for QK^T and PV).
// CTA = 128 q rows x 1 (b,h); 8 warps each own 16 q rows (full kv width).
// KV tiles of 128; causal tile skipping; P stays in registers (S D-frags
// map directly onto PV A-frags).
// ---------------------------------------------------------------------------
#define QSTRIDE 144            // 64 bf16 = 128B + 16B pad
#define VSTRIDE 272            // 128 bf16 = 256B + 16B pad
#define AQ_HI 0u
#define AQ_LO 18432u
#define AK_HI 36864u
#define AK_LO 55296u
#define AV_HI 73728u
#define AV_LO 91136u
#define ATT_SMEM 108544u

__global__ __launch_bounds__(256)
void attention_mma(const float* __restrict__ qkv, float* __restrict__ attn,
                   const int* __restrict__ causal_flag)
{
    extern __shared__ __align__(16) char sm[];
    const int tid  = threadIdx.x, wid = tid >> 5, lane = tid & 31;
    const int g    = lane >> 2, tg = lane & 3;
    const int qt   = (SEQ / 128 - 1) - blockIdx.x;   // long CTAs first
    const int bh   = blockIdx.y, b = bh / NH, h = bh % NH;
    const int causal = *causal_flag;
    const int q0   = qt * 128;

    const float* Qg = qkv + (size_t)(b * SEQ + q0) * NQKV + h * HD;
    const float* Kg = qkv + (size_t)(b * SEQ) * NQKV + EMB + h * HD;
    const float* Vg = qkv + (size_t)(b * SEQ) * NQKV + 2 * EMB + h * HD;

    // Load Q tile (128 x 64) once, hi/lo bf16 planes
#pragma unroll
    for (int it = 0; it < 8; it++) {
        int idx = tid + it * 256;
        int row = idx >> 4, c4 = (idx & 15) << 2;
        float4 v = *(const float4*)(Qg + (size_t)row * NQKV + c4);
        uint32_t h0, l0, h1, l1;
        packsplit(v.x, v.y, h0, l0);
        packsplit(v.z, v.w, h1, l1);
        uint32_t off = (uint32_t)(row * QSTRIDE + c4 * 2);
        *(uint2*)(sm + AQ_HI + off) = make_uint2(h0, h1);
        *(uint2*)(sm + AQ_LO + off) = make_uint2(l0, l1);
    }

    float o[8][4];
#pragma unroll
    for (int i = 0; i < 8; i++)
#pragma unroll
        for (int e = 0; e < 4; e++) o[i][e] = 0.0f;
    float m0v = -1e30f, m1v = -1e30f, l0v = 0.0f, l1v = 0.0f;

    const int nkv = causal ? (qt + 1) : (SEQ / 128);
    for (int kvt = 0; kvt < nkv; kvt++) {
        const int kv0 = kvt * 128;
        __syncthreads();   // previous tile's compute done before overwrite

        // Load K (row-major q-style) and V (transposed to [d][kv]) tiles
#pragma unroll
        for (int it = 0; it < 8; it++) {
            int idx = tid + it * 256;
            int row = idx >> 4, c4 = (idx & 15) << 2;
            float4 kvv = *(const float4*)(Kg + (size_t)(kv0 + row) * NQKV + c4);
            uint32_t h0, l0, h1, l1;
            packsplit(kvv.x, kvv.y, h0, l0);
            packsplit(kvv.z, kvv.w, h1, l1);
            uint32_t off = (uint32_t)(row * QSTRIDE + c4 * 2);
            *(uint2*)(sm + AK_HI + off) = make_uint2(h0, h1);
            *(uint2*)(sm + AK_LO + off) = make_uint2(l0, l1);

            float4 vv = *(const float4*)(Vg + (size_t)(kv0 + row) * NQKV + c4);
            float va[4] = {vv.x, vv.y, vv.z, vv.w};
#pragma unroll
            for (int j = 0; j < 4; j++) {
                uint32_t hb = f2bfbits(va[j]);
                uint32_t lb = f2bfbits(va[j] - bfbits2f(hb));
                uint32_t voff = (uint32_t)((c4 + j) * VSTRIDE + row * 2);
                *(unsigned short*)(sm + AV_HI + voff) = (unsigned short)hb;
                *(unsigned short*)(sm + AV_LO + voff) = (unsigned short)lb;
            }
        }
        __syncthreads();

        // ---- S = Q @ K^T (16 q-rows x 128 kv per warp) ----
        float s[16][4];
#pragma unroll
        for (int nf = 0; nf < 16; nf++)
#pragma unroll
            for (int e = 0; e < 4; e++) s[nf][e] = 0.0f;

#pragma unroll
        for (int ks = 0; ks < 4; ks++) {
            uint32_t ab = (uint32_t)((wid * 16 + g) * QSTRIDE + ks * 32 + tg * 4);
            uint32_t aH[4], aL[4];
            aH[0] = *(const uint32_t*)(sm + AQ_HI + ab);
            aH[1] = *(const uint32_t*)(sm + AQ_HI + ab + 8 * QSTRIDE);
            aH[2] = *(const uint32_t*)(sm + AQ_HI + ab + 16);
            aH[3] = *(const uint32_t*)(sm + AQ_HI + ab + 8 * QSTRIDE + 16);
            aL[0] = *(const uint32_t*)(sm + AQ_LO + ab);
            aL[1] = *(const uint32_t*)(sm + AQ_LO + ab + 8 * QSTRIDE);
            aL[2] = *(const uint32_t*)(sm + AQ_LO + ab + 16);
            aL[3] = *(const uint32_t*)(sm + AQ_LO + ab + 8 * QSTRIDE + 16);
#pragma unroll
            for (int nf = 0; nf < 16; nf++) {
                uint32_t bb = (uint32_t)((nf * 8 + g) * QSTRIDE + ks * 32 + tg * 4);
                uint32_t bH[2], bL[2];
                bH[0] = *(const uint32_t*)(sm + AK_HI + bb);
                bH[1] = *(const uint32_t*)(sm + AK_HI + bb + 16);
                bL[0] = *(const uint32_t*)(sm + AK_LO + bb);
                bL[1] = *(const uint32_t*)(sm + AK_LO + bb + 16);
                mma16816(s[nf], aH, bH);
                mma16816(s[nf], aH, bL);
                mma16816(s[nf], aL, bH);
            }
        }

        // ---- scale + causal mask (diagonal tile only) ----
        const bool dm = (causal != 0) && (kvt == qt);
#pragma unroll
        for (int nf = 0; nf < 16; nf++) {
#pragma unroll
            for (int e = 0; e < 4; e++) {
                float v = s[nf][e] * 0.125f;   // 1/sqrt(64)
                if (dm) {
                    int qr = wid * 16 + g + ((e >= 2) ? 8 : 0);
                    int kc = nf * 8 + tg * 2 + (e & 1);
                    if (kc > qr) v = -1e30f;
                }
                s[nf][e] = v;
            }
        }

        // ---- online softmax (rows g and g+8 per thread) ----
        float mx0 = -1e30f, mx1 = -1e30f;
#pragma unroll
        for (int nf = 0; nf < 16; nf++) {
            mx0 = fmaxf(mx0, fmaxf(s[nf][0], s[nf][1]));
            mx1 = fmaxf(mx1, fmaxf(s[nf][2], s[nf][3]));
        }
        mx0 = fmaxf(mx0, __shfl_xor_sync(0xffffffffu, mx0, 1));
        mx0 = fmaxf(mx0, __shfl_xor_sync(0xffffffffu, mx0, 2));
        mx1 = fmaxf(mx1, __shfl_xor_sync(0xffffffffu, mx1, 1));
        mx1 = fmaxf(mx1, __shfl_xor_sync(0xffffffffu, mx1, 2));

        float mn0 = fmaxf(m0v, mx0), mn1 = fmaxf(m1v, mx1);
        float al0 = __expf(m0v - mn0), al1 = __expf(m1v - mn1);
        m0v = mn0; m1v = mn1;

        float rs0 = 0.0f, rs1 = 0.0f;
#pragma unroll
        for (int nf = 0; nf < 16; nf++) {
            s[nf][0] = __expf(s[nf][0] - mn0); rs0 += s[nf][0];
            s[nf][1] = __expf(s[nf][1] - mn0); rs0 += s[nf][1];
            s[nf][2] = __expf(s[nf][2] - mn1); rs1 += s[nf][2];
            s[nf][3] = __expf(s[nf][3] - mn1); rs1 += s[nf][3];
        }
        rs0 += __shfl_xor_sync(0xffffffffu, rs0, 1);
        rs0 += __shfl_xor_sync(0xffffffffu, rs0, 2);
        rs1 += __shfl_xor_sync(0xffffffffu, rs1, 1);
        rs1 += __shfl_xor_sync(0xffffffffu, rs1, 2);
        l0v = l0v * al0 + rs0;
        l1v = l1v * al1 + rs1;

#pragma unroll
        for (int nf = 0; nf < 8; nf++) {
            o[nf][0] *= al0; o[nf][1] *= al0;
            o[nf][2] *= al1; o[nf][3] *= al1;
        }

        // ---- O += P @ V  (P from registers; S D-frags -> A-frags) ----
#pragma unroll
        for (int kf = 0; kf < 8; kf++) {
            uint32_t aH[4], aL[4];
            packsplit(s[2 * kf][0],     s[2 * kf][1],     aH[0], aL[0]);
            packsplit(s[2 * kf][2],     s[2 * kf][3],     aH[1], aL[1]);
            packsplit(s[2 * kf + 1][0], s[2 * kf + 1][1], aH[2], aL[2]);
            packsplit(s[2 * kf + 1][2], s[2 * kf + 1][3], aH[3], aL[3]);
#pragma unroll
            for (int nf = 0; nf < 8; nf++) {
                uint32_t vb = (uint32_t)((nf * 8 + g) * VSTRIDE + kf * 32 + tg * 4);
                uint32_t bH[2], bL[2];
                bH[0] = *(const uint32_t*)(sm + AV_HI + vb);
                bH[1] = *(const uint32_t*)(sm + AV_HI + vb + 16);
                bL[0] = *(const uint32_t*)(sm + AV_LO + vb);
                bL[1] = *(const uint32_t*)(sm + AV_LO + vb + 16);
                mma16816(o[nf], aH, bH);
                mma16816(o[nf], aH, bL);
                mma16816(o[nf], aL, bH);
            }
        }
    }

    // ---- normalize + write (b, s, h*64+d) ----
    const float inv0 = 1.0f / l0v, inv1 = 1.0f / l1v;
    const size_t r0 = (size_t)(b * SEQ + q0 + wid * 16 + g);
#pragma unroll
    for (int nf = 0; nf < 8; nf++) {
        int col = h * HD + nf * 8 + tg * 2;
        *(float2*)(attn + r0 * EMB + col) =
            make_float2(o[nf][0] * inv0, o[nf][1] * inv0);
        *(float2*)(attn + (r0 + 8) * EMB + col) =
            make_float2(o[nf][2] * inv1, o[nf][3] * inv1);
    }
}

// ---------------------------------------------------------------------------
extern "C" void kernel_launch(void* const* d_in, const int* in_sizes, int n_in,
                              void* d_out, int out_size)
{
    (void)in_sizes; (void)n_in; (void)out_size;
    const float* x      = (const float*)d_in[0];
    const float* w_qkv  = (const float*)d_in[1];
    const float* b_qkv  = (const float*)d_in[2];
    const float* w_out  = (const float*)d_in[3];
    const float* b_out  = (const float*)d_in[4];
    const int*   causal = (const int*)d_in[5];
    float* out = (float*)d_out;

    float *qkvbuf = nullptr, *attnbuf = nullptr;
    cudaGetSymbolAddress((void**)&qkvbuf, g_qkv);
    cudaGetSymbolAddress((void**)&attnbuf, g_attn);

    cudaFuncSetAttribute(gemm_mma, cudaFuncAttributeMaxDynamicSharedMemorySize,
                         (int)GEMM_SMEM);
    cudaFuncSetAttribute(attention_mma, cudaFuncAttributeMaxDynamicSharedMemorySize,
                         (int)ATT_SMEM);

    // QKV projection: [4096,1024] @ [3072,1024]^T -> [4096,3072]
    gemm_mma<<<dim3(NQKV / GBN, MTOT / GBM), 256, GEMM_SMEM>>>(
        x, w_qkv, b_qkv, qkvbuf, MTOT, NQKV, EMB);
    // Causal flash attention -> [4096,1024] in (b,s,e) layout
    attention_mma<<<dim3(SEQ / 128, BATCH * NH), 256, ATT_SMEM>>>(
        qkvbuf, attnbuf, causal);
    // Output projection: [4096,1024] @ [1024,1024]^T -> [4096,1024]
    gemm_mma<<<dim3(EMB / GBN, MTOT / GBM), 256, GEMM_SMEM>>>(
        attnbuf, w_out, b_out, out, MTOT, EMB, EMB);
}

// round 5
// speedup vs baseline: 2.8037x; 1.0001x over previous
#include <cuda_runtime.h>
#include <cuda_bf16.h>
#include <cstdint>

// Problem constants
#define BATCH 2
#define SEQ   2048
#define EMB   1024
#define NH    16
#define HD    64
#define MTOT  (BATCH * SEQ)     // 4096
#define NQKV  (3 * EMB)         // 3072

// Scratch (device globals: allocation-free rule)
__device__ float g_qkv[(size_t)MTOT * NQKV];   // [4096, 3072]
__device__ float g_attn[(size_t)MTOT * EMB];   // [4096, 1024]

// ---------------------------------------------------------------------------
// bf16 split helpers
// ---------------------------------------------------------------------------
__device__ __forceinline__ uint32_t f2bfbits(float x) {
    __nv_bfloat16 b = __float2bfloat16(x);
    return (uint32_t)*reinterpret_cast<unsigned short*>(&b);
}
__device__ __forceinline__ float bfbits2f(uint32_t b16) {
    return __uint_as_float(b16 << 16);
}
__device__ __forceinline__ uint32_t packbf(float x, float y) {
    return f2bfbits(x) | (f2bfbits(y) << 16);
}
// x,y -> (hi pair, lo pair) with x in low half
__device__ __forceinline__ void packsplit(float x, float y,
                                          uint32_t& hi, uint32_t& lo) {
    hi = packbf(x, y);
    lo = packbf(x - bfbits2f(hi & 0xffffu), y - bfbits2f(hi >> 16));
}

// mma.sync m16n8k16 bf16 (A row-major, B col-major), D += A*B
__device__ __forceinline__ void mma16816(float* d, const uint32_t* a,
                                         const uint32_t* b) {
    asm volatile(
        "mma.sync.aligned.m16n8k16.row.col.f32.bf16.bf16.f32 "
        "{%0,%1,%2,%3}, {%4,%5,%6,%7}, {%8,%9}, {%0,%1,%2,%3};"
        : "+f"(d[0]), "+f"(d[1]), "+f"(d[2]), "+f"(d[3])
        : "r"(a[0]), "r"(a[1]), "r"(a[2]), "r"(a[3]), "r"(b[0]), "r"(b[1]));
}

// ---------------------------------------------------------------------------
// GEMM via mma.sync, 3-term bf16 split: C[M,N] = A[M,K] @ W[N,K]^T + bias[N]
// CTA 128x128, BK=32, 8 warps (2m x 4n), warp tile 64x32.
// smem rows: 32 bf16 = 64B + 16B pad = 80B stride (conflict-free frag LDS).
// ---------------------------------------------------------------------------
#define GBM 128
#define GBN 128
#define GBK 32
#define GSTRIDE 80
#define GP_A_HI 0u
#define GP_A_LO 10240u
#define GP_B_HI 20480u
#define GP_B_LO 30720u
#define GSTAGE  40960u
#define GEMM_SMEM (2u * GSTAGE)   // 81920 bytes

__global__ __launch_bounds__(256)
void gemm_mma(const float* __restrict__ A, const float* __restrict__ W,
              const float* __restrict__ bias, float* __restrict__ C,
              int M, int N, int K)
{
    extern __shared__ __align__(16) char sm[];
    const int tid  = threadIdx.x;
    const int wid  = tid >> 5, lane = tid & 31;
    const int g    = lane >> 2, tg = lane & 3;
    const int m0   = blockIdx.y * GBM, n0 = blockIdx.x * GBN;
    const int m0w  = (wid >> 2) * 64, n0w = (wid & 3) * 32;

    const float* Ab = A + (size_t)m0 * K;
    const float* Wb = W + (size_t)n0 * K;

    float acc[4][4][4];
#pragma unroll
    for (int i = 0; i < 4; i++)
#pragma unroll
        for (int j = 0; j < 4; j++)
#pragma unroll
            for (int e = 0; e < 4; e++) acc[i][j][e] = 0.0f;

    float4 abuf[4], bbuf[4];

    auto ldg = [&](int kt) {
#pragma unroll
        for (int it = 0; it < 4; it++) {
            int idx = tid + it * 256;
            int row = idx >> 3, c4 = (idx & 7) << 2;
            abuf[it] = *(const float4*)(Ab + (size_t)row * K + kt + c4);
            bbuf[it] = *(const float4*)(Wb + (size_t)row * K + kt + c4);
        }
    };
    auto sts = [&](uint32_t so) {
#pragma unroll
        for (int it = 0; it < 4; it++) {
            int idx = tid + it * 256;
            int row = idx >> 3, c8 = (idx & 7) << 3;   // byte col offset
            uint32_t off = so + (uint32_t)(row * GSTRIDE + c8);
            uint32_t h0, l0, h1, l1;
            packsplit(abuf[it].x, abuf[it].y, h0, l0);
            packsplit(abuf[it].z, abuf[it].w, h1, l1);
            *(uint2*)(sm + GP_A_HI + off) = make_uint2(h0, h1);
            *(uint2*)(sm + GP_A_LO + off) = make_uint2(l0, l1);
            packsplit(bbuf[it].x, bbuf[it].y, h0, l0);
            packsplit(bbuf[it].z, bbuf[it].w, h1, l1);
            *(uint2*)(sm + GP_B_HI + off) = make_uint2(h0, h1);
            *(uint2*)(sm + GP_B_LO + off) = make_uint2(l0, l1);
        }
    };
    auto compute = [&](uint32_t so) {
#pragma unroll
        for (int ks = 0; ks < 2; ks++) {
            const uint32_t kb = (uint32_t)(ks * 32 + tg * 4);
            uint32_t aH[4][4], aL[4][4], bH[4][2], bL[4][2];
#pragma unroll
            for (int mf = 0; mf < 4; mf++) {
                uint32_t ab = so + (uint32_t)((m0w + mf * 16 + g) * GSTRIDE) + kb;
                aH[mf][0] = *(const uint32_t*)(sm + GP_A_HI + ab);
                aH[mf][1] = *(const uint32_t*)(sm + GP_A_HI + ab + 8 * GSTRIDE);
                aH[mf][2] = *(const uint32_t*)(sm + GP_A_HI + ab + 16);
                aH[mf][3] = *(const uint32_t*)(sm + GP_A_HI + ab + 8 * GSTRIDE + 16);
                aL[mf][0] = *(const uint32_t*)(sm + GP_A_LO + ab);
                aL[mf][1] = *(const uint32_t*)(sm + GP_A_LO + ab + 8 * GSTRIDE);
                aL[mf][2] = *(const uint32_t*)(sm + GP_A_LO + ab + 16);
                aL[mf][3] = *(const uint32_t*)(sm + GP_A_LO + ab + 8 * GSTRIDE + 16);
            }
#pragma unroll
            for (int nf = 0; nf < 4; nf++) {
                uint32_t bb = so + (uint32_t)((n0w + nf * 8 + g) * GSTRIDE) + kb;
                bH[nf][0] = *(const uint32_t*)(sm + GP_B_HI + bb);
                bH[nf][1] = *(const uint32_t*)(sm + GP_B_HI + bb + 16);
                bL[nf][0] = *(const uint32_t*)(sm + GP_B_LO + bb);
                bL[nf][1] = *(const uint32_t*)(sm + GP_B_LO + bb + 16);
            }
#pragma unroll
            for (int mf = 0; mf < 4; mf++)
#pragma unroll
                for (int nf = 0; nf < 4; nf++) {
                    mma16816(acc[mf][nf], aH[mf], bH[nf]);
                    mma16816(acc[mf][nf], aH[mf], bL[nf]);
                    mma16816(acc[mf][nf], aL[mf], bH[nf]);
                }
        }
    };

    ldg(0);
    sts(0);
    __syncthreads();

    const int NC = K / GBK;
    for (int c = 0; c < NC; c++) {
        uint32_t so = (uint32_t)(c & 1) * GSTAGE;
        if (c + 1 < NC) ldg((c + 1) * GBK);     // overlap LDG with mma
        compute(so);
        if (c + 1 < NC) sts((uint32_t)((c + 1) & 1) * GSTAGE);
        __syncthreads();
    }

    // epilogue: D frag c0,c1 = (row, col..col+1); c2,c3 = (row+8, ...)
#pragma unroll
    for (int mf = 0; mf < 4; mf++) {
        int r = m0 + m0w + mf * 16 + g;
#pragma unroll
        for (int nf = 0; nf < 4; nf++) {
            int col = n0 + n0w + nf * 8 + tg * 2;
            float b0 = bias[col], b1 = bias[col + 1];
            *(float2*)(C + (size_t)r * N + col) =
                make_float2(acc[mf][nf][0] + b0, acc[mf][nf][1] + b1);
            *(float2*)(C + (size_t)(r + 8) * N + col) =
                make_float2(acc[mf][nf][2] + b0, acc[mf][nf][3] + b1);
        }
    }
}

// ---------------------------------------------------------------------------
// Flash attention with mma.sync (3-term bf16 splits for QK^T and PV).
// CTA = 128 q rows x 1 (b,h); 8 warps each own 16 q rows (full kv width).
// KV tiles of 128; causal tile skipping; P stays in registers (S D-frags
// map directly onto PV A-frags).
// ---------------------------------------------------------------------------
#define QSTRIDE 144            // 64 bf16 = 128B + 16B pad
#define VSTRIDE 272            // 128 bf16 = 256B + 16B pad
#define AQ_HI 0u
#define AQ_LO 18432u
#define AK_HI 36864u
#define AK_LO 55296u
#define AV_HI 73728u
#define AV_LO 91136u
#define ATT_SMEM 108544u

__global__ __launch_bounds__(256)
void attention_mma(const float* __restrict__ qkv, float* __restrict__ attn,
                   const int* __restrict__ causal_flag)
{
    extern __shared__ __align__(16) char sm[];
    const int tid  = threadIdx.x, wid = tid >> 5, lane = tid & 31;
    const int g    = lane >> 2, tg = lane & 3;
    const int qt   = (SEQ / 128 - 1) - blockIdx.x;   // long CTAs first
    const int bh   = blockIdx.y, b = bh / NH, h = bh % NH;
    const int causal = *causal_flag;
    const int q0   = qt * 128;

    const float* Qg = qkv + (size_t)(b * SEQ + q0) * NQKV + h * HD;
    const float* Kg = qkv + (size_t)(b * SEQ) * NQKV + EMB + h * HD;
    const float* Vg = qkv + (size_t)(b * SEQ) * NQKV + 2 * EMB + h * HD;

    // Load Q tile (128 x 64) once, hi/lo bf16 planes
#pragma unroll
    for (int it = 0; it < 8; it++) {
        int idx = tid + it * 256;
        int row = idx >> 4, c4 = (idx & 15) << 2;
        float4 v = *(const float4*)(Qg + (size_t)row * NQKV + c4);
        uint32_t h0, l0, h1, l1;
        packsplit(v.x, v.y, h0, l0);
        packsplit(v.z, v.w, h1, l1);
        uint32_t off = (uint32_t)(row * QSTRIDE + c4 * 2);
        *(uint2*)(sm + AQ_HI + off) = make_uint2(h0, h1);
        *(uint2*)(sm + AQ_LO + off) = make_uint2(l0, l1);
    }

    float o[8][4];
#pragma unroll
    for (int i = 0; i < 8; i++)
#pragma unroll
        for (int e = 0; e < 4; e++) o[i][e] = 0.0f;
    float m0v = -1e30f, m1v = -1e30f, l0v = 0.0f, l1v = 0.0f;

    const int nkv = causal ? (qt + 1) : (SEQ / 128);
    for (int kvt = 0; kvt < nkv; kvt++) {
        const int kv0 = kvt * 128;
        __syncthreads();   // previous tile's compute done before overwrite

        // Load K (row-major q-style) and V (transposed to [d][kv]) tiles
#pragma unroll
        for (int it = 0; it < 8; it++) {
            int idx = tid + it * 256;
            int row = idx >> 4, c4 = (idx & 15) << 2;
            float4 kvv = *(const float4*)(Kg + (size_t)(kv0 + row) * NQKV + c4);
            uint32_t h0, l0, h1, l1;
            packsplit(kvv.x, kvv.y, h0, l0);
            packsplit(kvv.z, kvv.w, h1, l1);
            uint32_t off = (uint32_t)(row * QSTRIDE + c4 * 2);
            *(uint2*)(sm + AK_HI + off) = make_uint2(h0, h1);
            *(uint2*)(sm + AK_LO + off) = make_uint2(l0, l1);

            float4 vv = *(const float4*)(Vg + (size_t)(kv0 + row) * NQKV + c4);
            float va[4] = {vv.x, vv.y, vv.z, vv.w};
#pragma unroll
            for (int j = 0; j < 4; j++) {
                uint32_t hb = f2bfbits(va[j]);
                uint32_t lb = f2bfbits(va[j] - bfbits2f(hb));
                uint32_t voff = (uint32_t)((c4 + j) * VSTRIDE + row * 2);
                *(unsigned short*)(sm + AV_HI + voff) = (unsigned short)hb;
                *(unsigned short*)(sm + AV_LO + voff) = (unsigned short)lb;
            }
        }
        __syncthreads();

        // ---- S = Q @ K^T (16 q-rows x 128 kv per warp) ----
        float s[16][4];
#pragma unroll
        for (int nf = 0; nf < 16; nf++)
#pragma unroll
            for (int e = 0; e < 4; e++) s[nf][e] = 0.0f;

#pragma unroll
        for (int ks = 0; ks < 4; ks++) {
            uint32_t ab = (uint32_t)((wid * 16 + g) * QSTRIDE + ks * 32 + tg * 4);
            uint32_t aH[4], aL[4];
            aH[0] = *(const uint32_t*)(sm + AQ_HI + ab);
            aH[1] = *(const uint32_t*)(sm + AQ_HI + ab + 8 * QSTRIDE);
            aH[2] = *(const uint32_t*)(sm + AQ_HI + ab + 16);
            aH[3] = *(const uint32_t*)(sm + AQ_HI + ab + 8 * QSTRIDE + 16);
            aL[0] = *(const uint32_t*)(sm + AQ_LO + ab);
            aL[1] = *(const uint32_t*)(sm + AQ_LO + ab + 8 * QSTRIDE);
            aL[2] = *(const uint32_t*)(sm + AQ_LO + ab + 16);
            aL[3] = *(const uint32_t*)(sm + AQ_LO + ab + 8 * QSTRIDE + 16);
#pragma unroll
            for (int nf = 0; nf < 16; nf++) {
                uint32_t bb = (uint32_t)((nf * 8 + g) * QSTRIDE + ks * 32 + tg * 4);
                uint32_t bH[2], bL[2];
                bH[0] = *(const uint32_t*)(sm + AK_HI + bb);
                bH[1] = *(const uint32_t*)(sm + AK_HI + bb + 16);
                bL[0] = *(const uint32_t*)(sm + AK_LO + bb);
                bL[1] = *(const uint32_t*)(sm + AK_LO + bb + 16);
                mma16816(s[nf], aH, bH);
                mma16816(s[nf], aH, bL);
                mma16816(s[nf], aL, bH);
            }
        }

        // ---- scale + causal mask (diagonal tile only) ----
        const bool dm = (causal != 0) && (kvt == qt);
#pragma unroll
        for (int nf = 0; nf < 16; nf++) {
#pragma unroll
            for (int e = 0; e < 4; e++) {
                float v = s[nf][e] * 0.125f;   // 1/sqrt(64)
                if (dm) {
                    int qr = wid * 16 + g + ((e >= 2) ? 8 : 0);
                    int kc = nf * 8 + tg * 2 + (e & 1);
                    if (kc > qr) v = -1e30f;
                }
                s[nf][e] = v;
            }
        }

        // ---- online softmax (rows g and g+8 per thread) ----
        float mx0 = -1e30f, mx1 = -1e30f;
#pragma unroll
        for (int nf = 0; nf < 16; nf++) {
            mx0 = fmaxf(mx0, fmaxf(s[nf][0], s[nf][1]));
            mx1 = fmaxf(mx1, fmaxf(s[nf][2], s[nf][3]));
        }
        mx0 = fmaxf(mx0, __shfl_xor_sync(0xffffffffu, mx0, 1));
        mx0 = fmaxf(mx0, __shfl_xor_sync(0xffffffffu, mx0, 2));
        mx1 = fmaxf(mx1, __shfl_xor_sync(0xffffffffu, mx1, 1));
        mx1 = fmaxf(mx1, __shfl_xor_sync(0xffffffffu, mx1, 2));

        float mn0 = fmaxf(m0v, mx0), mn1 = fmaxf(m1v, mx1);
        float al0 = __expf(m0v - mn0), al1 = __expf(m1v - mn1);
        m0v = mn0; m1v = mn1;

        float rs0 = 0.0f, rs1 = 0.0f;
#pragma unroll
        for (int nf = 0; nf < 16; nf++) {
            s[nf][0] = __expf(s[nf][0] - mn0); rs0 += s[nf][0];
            s[nf][1] = __expf(s[nf][1] - mn0); rs0 += s[nf][1];
            s[nf][2] = __expf(s[nf][2] - mn1); rs1 += s[nf][2];
            s[nf][3] = __expf(s[nf][3] - mn1); rs1 += s[nf][3];
        }
        rs0 += __shfl_xor_sync(0xffffffffu, rs0, 1);
        rs0 += __shfl_xor_sync(0xffffffffu, rs0, 2);
        rs1 += __shfl_xor_sync(0xffffffffu, rs1, 1);
        rs1 += __shfl_xor_sync(0xffffffffu, rs1, 2);
        l0v = l0v * al0 + rs0;
        l1v = l1v * al1 + rs1;

#pragma unroll
        for (int nf = 0; nf < 8; nf++) {
            o[nf][0] *= al0; o[nf][1] *= al0;
            o[nf][2] *= al1; o[nf][3] *= al1;
        }

        // ---- O += P @ V  (P from registers; S D-frags -> A-frags) ----
#pragma unroll
        for (int kf = 0; kf < 8; kf++) {
            uint32_t aH[4], aL[4];
            packsplit(s[2 * kf][0],     s[2 * kf][1],     aH[0], aL[0]);
            packsplit(s[2 * kf][2],     s[2 * kf][3],     aH[1], aL[1]);
            packsplit(s[2 * kf + 1][0], s[2 * kf + 1][1], aH[2], aL[2]);
            packsplit(s[2 * kf + 1][2], s[2 * kf + 1][3], aH[3], aL[3]);
#pragma unroll
            for (int nf = 0; nf < 8; nf++) {
                uint32_t vb = (uint32_t)((nf * 8 + g) * VSTRIDE + kf * 32 + tg * 4);
                uint32_t bH[2], bL[2];
                bH[0] = *(const uint32_t*)(sm + AV_HI + vb);
                bH[1] = *(const uint32_t*)(sm + AV_HI + vb + 16);
                bL[0] = *(const uint32_t*)(sm + AV_LO + vb);
                bL[1] = *(const uint32_t*)(sm + AV_LO + vb + 16);
                mma16816(o[nf], aH, bH);
                mma16816(o[nf], aH, bL);
                mma16816(o[nf], aL, bH);
            }
        }
    }

    // ---- normalize + write (b, s, h*64+d) ----
    const float inv0 = 1.0f / l0v, inv1 = 1.0f / l1v;
    const size_t r0 = (size_t)(b * SEQ + q0 + wid * 16 + g);
#pragma unroll
    for (int nf = 0; nf < 8; nf++) {
        int col = h * HD + nf * 8 + tg * 2;
        *(float2*)(attn + r0 * EMB + col) =
            make_float2(o[nf][0] * inv0, o[nf][1] * inv0);
        *(float2*)(attn + (r0 + 8) * EMB + col) =
            make_float2(o[nf][2] * inv1, o[nf][3] * inv1);
    }
}

// ---------------------------------------------------------------------------
extern "C" void kernel_launch(void* const* d_in, const int* in_sizes, int n_in,
                              void* d_out, int out_size)
{
    (void)in_sizes; (void)n_in; (void)out_size;
    const float* x      = (const float*)d_in[0];
    const float* w_qkv  = (const float*)d_in[1];
    const float* b_qkv  = (const float*)d_in[2];
    const float* w_out  = (const float*)d_in[3];
    const float* b_out  = (const float*)d_in[4];
    const int*   causal = (const int*)d_in[5];
    float* out = (float*)d_out;

    float *qkvbuf = nullptr, *attnbuf = nullptr;
    cudaGetSymbolAddress((void**)&qkvbuf, g_qkv);
    cudaGetSymbolAddress((void**)&attnbuf, g_attn);

    cudaFuncSetAttribute(gemm_mma, cudaFuncAttributeMaxDynamicSharedMemorySize,
                         (int)GEMM_SMEM);
    cudaFuncSetAttribute(attention_mma, cudaFuncAttributeMaxDynamicSharedMemorySize,
                         (int)ATT_SMEM);

    // QKV projection: [4096,1024] @ [3072,1024]^T -> [4096,3072]
    gemm_mma<<<dim3(NQKV / GBN, MTOT / GBM), 256, GEMM_SMEM>>>(
        x, w_qkv, b_qkv, qkvbuf, MTOT, NQKV, EMB);
    // Causal flash attention -> [4096,1024] in (b,s,e) layout
    attention_mma<<<dim3(SEQ / 128, BATCH * NH), 256, ATT_SMEM>>>(
        qkvbuf, attnbuf, causal);
    // Output projection: [4096,1024] @ [1024,1024]^T -> [4096,1024]
    gemm_mma<<<dim3(EMB / GBN, MTOT / GBM), 256, GEMM_SMEM>>>(
        attnbuf, w_out, b_out, out, MTOT, EMB, EMB);
}

// round 6
// speedup vs baseline: 3.5579x; 1.2690x over previous
#include <cuda_runtime.h>
#include <cuda_bf16.h>
#include <cstdint>

typedef __nv_bfloat16 bf16;

// Problem constants
#define BATCH 2
#define SEQ   2048
#define EMB   1024
#define NH    16
#define HD    64
#define MTOT  (BATCH * SEQ)     // 4096
#define NQKV  (3 * EMB)         // 3072

// ---------------------------------------------------------------------------
// Device-global scratch (allocation-free rule)
// ---------------------------------------------------------------------------
__device__ bf16 g_xh[(size_t)MTOT * EMB],  g_xl[(size_t)MTOT * EMB];
__device__ bf16 g_wqh[(size_t)NQKV * EMB], g_wql[(size_t)NQKV * EMB];
__device__ bf16 g_woh[(size_t)EMB * EMB],  g_wol[(size_t)EMB * EMB];
__device__ bf16 g_qkh[(size_t)MTOT * 2048], g_qkl[(size_t)MTOT * 2048];  // Q|K planes
__device__ bf16 g_vth[(size_t)BATCH * NH * HD * SEQ], g_vtl[(size_t)BATCH * NH * HD * SEQ];
__device__ bf16 g_ath[(size_t)MTOT * EMB], g_atl[(size_t)MTOT * EMB];    // attn out planes

// ---------------------------------------------------------------------------
// Helpers
// ---------------------------------------------------------------------------
__device__ __forceinline__ uint32_t smem_u32(const void* p) {
    uint32_t a;
    asm("{ .reg .u64 t; cvta.to.shared.u64 t, %1; cvt.u32.u64 %0, t; }"
        : "=r"(a) : "l"(p));
    return a;
}
__device__ __forceinline__ uint32_t f2bfbits(float x) {
    bf16 b = __float2bfloat16(x);
    return (uint32_t)*reinterpret_cast<unsigned short*>(&b);
}
__device__ __forceinline__ float bfbits2f(uint32_t b16) {
    return __uint_as_float(b16 << 16);
}
__device__ __forceinline__ uint32_t packbf(float x, float y) {
    return f2bfbits(x) | (f2bfbits(y) << 16);
}
__device__ __forceinline__ void packsplit(float x, float y,
                                          uint32_t& hi, uint32_t& lo) {
    hi = packbf(x, y);
    lo = packbf(x - bfbits2f(hi & 0xffffu), y - bfbits2f(hi >> 16));
}

__device__ __forceinline__ void mma16816(float* d, const uint32_t* a,
                                         const uint32_t* b) {
    asm volatile(
        "mma.sync.aligned.m16n8k16.row.col.f32.bf16.bf16.f32 "
        "{%0,%1,%2,%3}, {%4,%5,%6,%7}, {%8,%9}, {%0,%1,%2,%3};"
        : "+f"(d[0]), "+f"(d[1]), "+f"(d[2]), "+f"(d[3])
        : "r"(a[0]), "r"(a[1]), "r"(a[2]), "r"(a[3]), "r"(b[0]), "r"(b[1]));
}
__device__ __forceinline__ void ldm_x4(uint32_t* r, uint32_t addr) {
    asm volatile("ldmatrix.sync.aligned.m8n8.x4.shared.b16 {%0,%1,%2,%3}, [%4];"
                 : "=r"(r[0]), "=r"(r[1]), "=r"(r[2]), "=r"(r[3]) : "r"(addr));
}
__device__ __forceinline__ void ldm_x2(uint32_t* r, uint32_t addr) {
    asm volatile("ldmatrix.sync.aligned.m8n8.x2.shared.b16 {%0,%1}, [%2];"
                 : "=r"(r[0]), "=r"(r[1]) : "r"(addr));
}
__device__ __forceinline__ void cpa16(uint32_t dst, const void* src) {
    asm volatile("cp.async.cg.shared.global [%0], [%1], 16;" :: "r"(dst), "l"(src));
}
__device__ __forceinline__ void cp_commit() {
    asm volatile("cp.async.commit_group;" ::: "memory");
}
template <int N>
__device__ __forceinline__ void cp_wait() {
    asm volatile("cp.async.wait_group %0;" :: "n"(N) : "memory");
}

// ---------------------------------------------------------------------------
// Pre-convert: fp32 -> (hi, lo) bf16 planes
// ---------------------------------------------------------------------------
__global__ void convert_split_k(const float4* __restrict__ in,
                                uint2* __restrict__ hi, uint2* __restrict__ lo,
                                int n4)
{
    int i = blockIdx.x * blockDim.x + threadIdx.x;
    if (i >= n4) return;
    float4 v = in[i];
    uint32_t h0, l0, h1, l1;
    packsplit(v.x, v.y, h0, l0);
    packsplit(v.z, v.w, h1, l1);
    hi[i] = make_uint2(h0, h1);
    lo[i] = make_uint2(l0, l1);
}

// ---------------------------------------------------------------------------
// bf16 3-term-split GEMM: C[M,N] = A[M,K] @ W[N,K]^T + bias[N]
// A,B given as hi/lo bf16 planes. CTA 128x128, BK=32, 8 warps (2m x 4n).
// cp.async 2-stage ring; ldmatrix frags; 80B smem row stride.
// MODE 0: fp32 C out.  MODE 1: QKV out (Q/K planes + V transposed planes).
// ---------------------------------------------------------------------------
#define GBM 128
#define GBN 128
#define GBK 32
#define GP_A_LO 10240u
#define GP_B_HI 20480u
#define GP_B_LO 30720u
#define GSTAGE  40960u
#define GEMM_SMEM (2u * GSTAGE)   // 81920 bytes

template <int MODE>
__global__ __launch_bounds__(256, 2)
void gemm_bf3(const bf16* __restrict__ Ah, const bf16* __restrict__ Al,
              const bf16* __restrict__ Bh, const bf16* __restrict__ Bl,
              const float* __restrict__ bias, float* __restrict__ C,
              bf16* __restrict__ qkh, bf16* __restrict__ qkl,
              bf16* __restrict__ vth, bf16* __restrict__ vtl,
              int M, int N, int K)
{
    extern __shared__ __align__(16) char sm[];
    const uint32_t sb = smem_u32(sm);
    const int tid = threadIdx.x;
    const int wid = tid >> 5, lane = tid & 31;
    const int g = lane >> 2, tg = lane & 3;
    const int m0 = blockIdx.y * GBM, n0 = blockIdx.x * GBN;
    const int m0w = (wid >> 2) * 64, n0w = (wid & 3) * 32;

    float acc[4][4][4];
#pragma unroll
    for (int i = 0; i < 4; i++)
#pragma unroll
        for (int j = 0; j < 4; j++)
#pragma unroll
            for (int e = 0; e < 4; e++) acc[i][j][e] = 0.0f;

    auto load_stage = [&](int c, uint32_t so) {
        const int kt = c * GBK;
#pragma unroll
        for (int i = 0; i < 4; i++) {                 // A: 1024 16B chunks
            int ci = tid + i * 256;
            int row = ci >> 3, sub = ci & 7;
            int pl = sub >> 2, kc = sub & 3;
            const bf16* src = (pl ? Al : Ah) + (size_t)(m0 + row) * K + kt + kc * 8;
            cpa16(sb + so + (pl ? GP_A_LO : 0u) + (uint32_t)(row * 80 + kc * 16), src);
        }
#pragma unroll
        for (int i = 0; i < 4; i++) {                 // B: 1024 16B chunks
            int ci = tid + i * 256;
            int row = ci >> 3, sub = ci & 7;
            int pl = sub >> 2, kc = sub & 3;
            const bf16* src = (pl ? Bl : Bh) + (size_t)(n0 + row) * K + kt + kc * 8;
            cpa16(sb + so + (pl ? GP_B_LO : GP_B_HI) + (uint32_t)(row * 80 + kc * 16), src);
        }
        cp_commit();
    };

    auto compute = [&](uint32_t so) {
#pragma unroll
        for (int ks = 0; ks < 2; ks++) {
            const uint32_t kb = (uint32_t)(ks * 32);
            uint32_t aH[4][4], aL[4][4];
#pragma unroll
            for (int mf = 0; mf < 4; mf++) {
                uint32_t ad = sb + so +
                    (uint32_t)((m0w + mf * 16 + (lane & 15)) * 80) +
                    kb + (uint32_t)((lane >> 4) * 16);
                ldm_x4(aH[mf], ad);
                ldm_x4(aL[mf], ad + GP_A_LO);
            }
#pragma unroll
            for (int nf = 0; nf < 4; nf++) {
                uint32_t bd = sb + so + GP_B_HI +
                    (uint32_t)((n0w + nf * 8 + (lane & 7)) * 80) +
                    kb + (uint32_t)(((lane >> 3) & 1) * 16);
                uint32_t bH[2], bL[2];
                ldm_x2(bH, bd);
                ldm_x2(bL, bd + 10240u);
#pragma unroll
                for (int mf = 0; mf < 4; mf++) {
                    mma16816(acc[mf][nf], aH[mf], bH);
                    mma16816(acc[mf][nf], aH[mf], bL);
                    mma16816(acc[mf][nf], aL[mf], bH);
                }
            }
        }
    };

    load_stage(0, 0);
    const int NC = K / GBK;
    for (int c = 0; c < NC; c++) {
        const uint32_t so = (uint32_t)(c & 1) * GSTAGE;
        if (c + 1 < NC) {
            load_stage(c + 1, (uint32_t)((c + 1) & 1) * GSTAGE);
            cp_wait<1>();
        } else {
            cp_wait<0>();
        }
        __syncthreads();
        compute(so);
        __syncthreads();
    }

    // ---- epilogue ----
#pragma unroll
    for (int mf = 0; mf < 4; mf++) {
        const int r = m0 + m0w + mf * 16 + g;
#pragma unroll
        for (int nf = 0; nf < 4; nf++) {
            const int col = n0 + n0w + nf * 8 + tg * 2;
            const float b0 = bias[col], b1 = bias[col + 1];
#pragma unroll
            for (int half = 0; half < 2; half++) {
                const int rr = r + half * 8;
                const float v0 = acc[mf][nf][half * 2 + 0] + b0;
                const float v1 = acc[mf][nf][half * 2 + 1] + b1;
                if (MODE == 0) {
                    *(float2*)(C + (size_t)rr * N + col) = make_float2(v0, v1);
                } else {
                    if (col < 2048) {
                        uint32_t hi, lo;
                        packsplit(v0, v1, hi, lo);
                        *(uint32_t*)(qkh + (size_t)rr * 2048 + col) = hi;
                        *(uint32_t*)(qkl + (size_t)rr * 2048 + col) = lo;
                    } else {
                        const int d = col - 2048;
                        const int hh = d >> 6, dd = d & 63;
                        const int bb = rr >> 11, rs = rr & 2047;
                        const size_t vb =
                            ((size_t)(bb * NH + hh) * HD + dd) * SEQ + rs;
                        uint32_t h0 = f2bfbits(v0);
                        vth[vb] = *reinterpret_cast<bf16*>(&h0);
                        uint32_t l0 = f2bfbits(v0 - bfbits2f(h0));
                        vtl[vb] = *reinterpret_cast<bf16*>(&l0);
                        uint32_t h1 = f2bfbits(v1);
                        vth[vb + SEQ] = *reinterpret_cast<bf16*>(&h1);
                        uint32_t l1 = f2bfbits(v1 - bfbits2f(h1));
                        vtl[vb + SEQ] = *reinterpret_cast<bf16*>(&l1);
                    }
                }
            }
        }
    }
}

// ---------------------------------------------------------------------------
// Flash attention, bf16 3-term split, cp.async + ldmatrix.
// CTA = 128 q rows x (b,h); 8 warps x 16 q rows; KV tiles of 128.
// Inputs: Q/K hi-lo planes [4096][2048], V transposed planes [b*h][64][2048].
// Output: hi/lo planes of O into g_ath/g_atl.
// ---------------------------------------------------------------------------
#define AQ_LO 18432u
#define AK_HI 36864u
#define AK_LO 55296u
#define AV_HI 73728u
#define AV_LO 91136u
#define ATT_SMEM 108544u
// Q/K row stride 144B (64 bf16 + pad), V row stride 272B (128 bf16 + pad)

__global__ __launch_bounds__(256)
void attention_mma(const bf16* __restrict__ qkh, const bf16* __restrict__ qkl,
                   const bf16* __restrict__ vth, const bf16* __restrict__ vtl,
                   bf16* __restrict__ ath, bf16* __restrict__ atl,
                   const int* __restrict__ causal_flag)
{
    extern __shared__ __align__(16) char sm[];
    const uint32_t sb = smem_u32(sm);
    const int tid = threadIdx.x, wid = tid >> 5, lane = tid & 31;
    const int g = lane >> 2, tg = lane & 3;
    const int qt = (SEQ / 128 - 1) - blockIdx.x;   // long CTAs first
    const int bh = blockIdx.y, b = bh / NH, h = bh % NH;
    const int causal = *causal_flag;
    const int q0 = qt * 128;

    // ---- Q tile load (once): 2048 chunks of 16B ----
#pragma unroll
    for (int i = 0; i < 8; i++) {
        int ci = tid + i * 256;
        int row = ci >> 4, sub = ci & 15;
        int pl = sub >> 3, kc = sub & 7;
        const bf16* src = (pl ? qkl : qkh) +
            (size_t)(b * SEQ + q0 + row) * 2048 + h * HD + kc * 8;
        cpa16(sb + (pl ? AQ_LO : 0u) + (uint32_t)(row * 144 + kc * 16), src);
    }
    cp_commit();

    float o[8][4];
#pragma unroll
    for (int i = 0; i < 8; i++)
#pragma unroll
        for (int e = 0; e < 4; e++) o[i][e] = 0.0f;
    float m0v = -1e30f, m1v = -1e30f, l0v = 0.0f, l1v = 0.0f;

    const int nkv = causal ? (qt + 1) : (SEQ / 128);
    for (int kvt = 0; kvt < nkv; kvt++) {
        const int kv0 = kvt * 128;
        __syncthreads();   // previous tile's smem reads done

        // K: 2048 chunks; V: 2048 chunks
#pragma unroll
        for (int i = 0; i < 8; i++) {
            int ci = tid + i * 256;
            int row = ci >> 4, sub = ci & 15;
            int pl = sub >> 3, kc = sub & 7;
            const bf16* src = (pl ? qkl : qkh) +
                (size_t)(b * SEQ + kv0 + row) * 2048 + 1024 + h * HD + kc * 8;
            cpa16(sb + (pl ? AK_LO : AK_HI) + (uint32_t)(row * 144 + kc * 16), src);
        }
#pragma unroll
        for (int i = 0; i < 8; i++) {
            int ci = tid + i * 256;
            int pl = ci >> 10, rem = ci & 1023;
            int row = rem >> 4, kc = rem & 15;
            const bf16* src = (pl ? vtl : vth) +
                ((size_t)bh * HD + row) * SEQ + kv0 + kc * 8;
            cpa16(sb + (pl ? AV_LO : AV_HI) + (uint32_t)(row * 272 + kc * 16), src);
        }
        cp_commit();
        cp_wait<0>();
        __syncthreads();

        // ---- S = Q @ K^T ----
        float s[16][4];
#pragma unroll
        for (int nf = 0; nf < 16; nf++)
#pragma unroll
            for (int e = 0; e < 4; e++) s[nf][e] = 0.0f;

#pragma unroll
        for (int ks = 0; ks < 4; ks++) {
            const uint32_t kb = (uint32_t)(ks * 32);
            uint32_t aH[4], aL[4];
            uint32_t ad = sb + (uint32_t)((wid * 16 + (lane & 15)) * 144) +
                          kb + (uint32_t)((lane >> 4) * 16);
            ldm_x4(aH, ad);
            ldm_x4(aL, ad + AQ_LO);
#pragma unroll
            for (int nf = 0; nf < 16; nf++) {
                uint32_t bd = sb + AK_HI +
                    (uint32_t)((nf * 8 + (lane & 7)) * 144) +
                    kb + (uint32_t)(((lane >> 3) & 1) * 16);
                uint32_t bH[2], bL[2];
                ldm_x2(bH, bd);
                ldm_x2(bL, bd + 18432u);
                mma16816(s[nf], aH, bH);
                mma16816(s[nf], aH, bL);
                mma16816(s[nf], aL, bH);
            }
        }

        // ---- scale + causal mask (diagonal tile only) ----
        const bool dm = (causal != 0) && (kvt == qt);
#pragma unroll
        for (int nf = 0; nf < 16; nf++) {
#pragma unroll
            for (int e = 0; e < 4; e++) {
                float v = s[nf][e] * 0.125f;   // 1/sqrt(64)
                if (dm) {
                    int qr = wid * 16 + g + ((e >= 2) ? 8 : 0);
                    int kc = nf * 8 + tg * 2 + (e & 1);
                    if (kc > qr) v = -1e30f;
                }
                s[nf][e] = v;
            }
        }

        // ---- online softmax (rows g and g+8) ----
        float mx0 = -1e30f, mx1 = -1e30f;
#pragma unroll
        for (int nf = 0; nf < 16; nf++) {
            mx0 = fmaxf(mx0, fmaxf(s[nf][0], s[nf][1]));
            mx1 = fmaxf(mx1, fmaxf(s[nf][2], s[nf][3]));
        }
        mx0 = fmaxf(mx0, __shfl_xor_sync(0xffffffffu, mx0, 1));
        mx0 = fmaxf(mx0, __shfl_xor_sync(0xffffffffu, mx0, 2));
        mx1 = fmaxf(mx1, __shfl_xor_sync(0xffffffffu, mx1, 1));
        mx1 = fmaxf(mx1, __shfl_xor_sync(0xffffffffu, mx1, 2));

        const float mn0 = fmaxf(m0v, mx0), mn1 = fmaxf(m1v, mx1);
        const float al0 = __expf(m0v - mn0), al1 = __expf(m1v - mn1);
        m0v = mn0; m1v = mn1;

        float rs0 = 0.0f, rs1 = 0.0f;
#pragma unroll
        for (int nf = 0; nf < 16; nf++) {
            s[nf][0] = __expf(s[nf][0] - mn0); rs0 += s[nf][0];
            s[nf][1] = __expf(s[nf][1] - mn0); rs0 += s[nf][1];
            s[nf][2] = __expf(s[nf][2] - mn1); rs1 += s[nf][2];
            s[nf][3] = __expf(s[nf][3] - mn1); rs1 += s[nf][3];
        }
        rs0 += __shfl_xor_sync(0xffffffffu, rs0, 1);
        rs0 += __shfl_xor_sync(0xffffffffu, rs0, 2);
        rs1 += __shfl_xor_sync(0xffffffffu, rs1, 1);
        rs1 += __shfl_xor_sync(0xffffffffu, rs1, 2);
        l0v = l0v * al0 + rs0;
        l1v = l1v * al1 + rs1;

#pragma unroll
        for (int nf = 0; nf < 8; nf++) {
            o[nf][0] *= al0; o[nf][1] *= al0;
            o[nf][2] *= al1; o[nf][3] *= al1;
        }

        // ---- O += P @ V (P split from registers; V^T frags via ldmatrix) ----
#pragma unroll
        for (int kf = 0; kf < 8; kf++) {
            uint32_t aH[4], aL[4];
            packsplit(s[2 * kf][0],     s[2 * kf][1],     aH[0], aL[0]);
            packsplit(s[2 * kf][2],     s[2 * kf][3],     aH[1], aL[1]);
            packsplit(s[2 * kf + 1][0], s[2 * kf + 1][1], aH[2], aL[2]);
            packsplit(s[2 * kf + 1][2], s[2 * kf + 1][3], aH[3], aL[3]);
#pragma unroll
            for (int nf = 0; nf < 8; nf++) {
                uint32_t vd = sb + AV_HI +
                    (uint32_t)((nf * 8 + (lane & 7)) * 272) +
                    (uint32_t)(kf * 32) + (uint32_t)(((lane >> 3) & 1) * 16);
                uint32_t bH[2], bL[2];
                ldm_x2(bH, vd);
                ldm_x2(bL, vd + 17408u);
                mma16816(o[nf], aH, bH);
                mma16816(o[nf], aH, bL);
                mma16816(o[nf], aL, bH);
            }
        }
    }

    // ---- normalize + write hi/lo planes of O ----
    const float inv0 = 1.0f / l0v, inv1 = 1.0f / l1v;
    const size_t r0 = (size_t)(b * SEQ + q0 + wid * 16 + g);
#pragma unroll
    for (int nf = 0; nf < 8; nf++) {
        const int col = h * HD + nf * 8 + tg * 2;
        uint32_t hi, lo;
        packsplit(o[nf][0] * inv0, o[nf][1] * inv0, hi, lo);
        *(uint32_t*)(ath + r0 * EMB + col) = hi;
        *(uint32_t*)(atl + r0 * EMB + col) = lo;
        packsplit(o[nf][2] * inv1, o[nf][3] * inv1, hi, lo);
        *(uint32_t*)(ath + (r0 + 8) * EMB + col) = hi;
        *(uint32_t*)(atl + (r0 + 8) * EMB + col) = lo;
    }
}

// ---------------------------------------------------------------------------
extern "C" void kernel_launch(void* const* d_in, const int* in_sizes, int n_in,
                              void* d_out, int out_size)
{
    (void)in_sizes; (void)n_in; (void)out_size;
    const float* x      = (const float*)d_in[0];
    const float* w_qkv  = (const float*)d_in[1];
    const float* b_qkv  = (const float*)d_in[2];
    const float* w_out  = (const float*)d_in[3];
    const float* b_out  = (const float*)d_in[4];
    const int*   causal = (const int*)d_in[5];
    float* out = (float*)d_out;

    bf16 *xh, *xl, *wqh, *wql, *woh, *wol, *qkh, *qkl, *vth, *vtl, *ath, *atl;
    cudaGetSymbolAddress((void**)&xh,  g_xh);   cudaGetSymbolAddress((void**)&xl,  g_xl);
    cudaGetSymbolAddress((void**)&wqh, g_wqh);  cudaGetSymbolAddress((void**)&wql, g_wql);
    cudaGetSymbolAddress((void**)&woh, g_woh);  cudaGetSymbolAddress((void**)&wol, g_wol);
    cudaGetSymbolAddress((void**)&qkh, g_qkh);  cudaGetSymbolAddress((void**)&qkl, g_qkl);
    cudaGetSymbolAddress((void**)&vth, g_vth);  cudaGetSymbolAddress((void**)&vtl, g_vtl);
    cudaGetSymbolAddress((void**)&ath, g_ath);  cudaGetSymbolAddress((void**)&atl, g_atl);

    cudaFuncSetAttribute(gemm_bf3<0>, cudaFuncAttributeMaxDynamicSharedMemorySize,
                         (int)GEMM_SMEM);
    cudaFuncSetAttribute(gemm_bf3<1>, cudaFuncAttributeMaxDynamicSharedMemorySize,
                         (int)GEMM_SMEM);
    cudaFuncSetAttribute(attention_mma, cudaFuncAttributeMaxDynamicSharedMemorySize,
                         (int)ATT_SMEM);

    // 1) pre-convert inputs to bf16 hi/lo planes
    convert_split_k<<<(MTOT * EMB / 4 + 255) / 256, 256>>>(
        (const float4*)x, (uint2*)xh, (uint2*)xl, MTOT * EMB / 4);
    convert_split_k<<<(NQKV * EMB / 4 + 255) / 256, 256>>>(
        (const float4*)w_qkv, (uint2*)wqh, (uint2*)wql, NQKV * EMB / 4);
    convert_split_k<<<(EMB * EMB / 4 + 255) / 256, 256>>>(
        (const float4*)w_out, (uint2*)woh, (uint2*)wol, EMB * EMB / 4);

    // 2) QKV projection -> Q/K planes + transposed V planes
    gemm_bf3<1><<<dim3(NQKV / GBN, MTOT / GBM), 256, GEMM_SMEM>>>(
        xh, xl, wqh, wql, b_qkv, nullptr, qkh, qkl, vth, vtl, MTOT, NQKV, EMB);

    // 3) causal flash attention -> O hi/lo planes
    attention_mma<<<dim3(SEQ / 128, BATCH * NH), 256, ATT_SMEM>>>(
        qkh, qkl, vth, vtl, ath, atl, causal);

    // 4) output projection -> fp32 out
    gemm_bf3<0><<<dim3(EMB / GBN, MTOT / GBM), 256, GEMM_SMEM>>>(
        ath, atl, woh, wol, b_out, out, nullptr, nullptr, nullptr, nullptr,
        MTOT, EMB, EMB);
}

// round 7
// speedup vs baseline: 3.6292x; 1.0200x over previous
#include <cuda_runtime.h>
#include <cuda_bf16.h>
#include <cstdint>

typedef __nv_bfloat16 bf16;

// Problem constants
#define BATCH 2
#define SEQ   2048
#define EMB   1024
#define NH    16
#define HD    64
#define MTOT  (BATCH * SEQ)     // 4096
#define NQKV  (3 * EMB)         // 3072

// ---------------------------------------------------------------------------
// Device-global scratch (allocation-free rule)
// ---------------------------------------------------------------------------
__device__ bf16 g_xh[(size_t)MTOT * EMB],  g_xl[(size_t)MTOT * EMB];
__device__ bf16 g_wqh[(size_t)NQKV * EMB], g_wql[(size_t)NQKV * EMB];
__device__ bf16 g_woh[(size_t)EMB * EMB],  g_wol[(size_t)EMB * EMB];
__device__ bf16 g_qkh[(size_t)MTOT * 2048], g_qkl[(size_t)MTOT * 2048];  // Q|K planes
__device__ bf16 g_vth[(size_t)BATCH * NH * HD * SEQ], g_vtl[(size_t)BATCH * NH * HD * SEQ];
__device__ bf16 g_ath[(size_t)MTOT * EMB], g_atl[(size_t)MTOT * EMB];    // attn out planes

// ---------------------------------------------------------------------------
// Helpers
// ---------------------------------------------------------------------------
__device__ __forceinline__ uint32_t smem_u32(const void* p) {
    uint32_t a;
    asm("{ .reg .u64 t; cvta.to.shared.u64 t, %1; cvt.u32.u64 %0, t; }"
        : "=r"(a) : "l"(p));
    return a;
}
__device__ __forceinline__ uint32_t f2bfbits(float x) {
    bf16 b = __float2bfloat16(x);
    return (uint32_t)*reinterpret_cast<unsigned short*>(&b);
}
__device__ __forceinline__ float bfbits2f(uint32_t b16) {
    return __uint_as_float(b16 << 16);
}
__device__ __forceinline__ uint32_t packbf(float x, float y) {
    return f2bfbits(x) | (f2bfbits(y) << 16);
}
__device__ __forceinline__ void packsplit(float x, float y,
                                          uint32_t& hi, uint32_t& lo) {
    hi = packbf(x, y);
    lo = packbf(x - bfbits2f(hi & 0xffffu), y - bfbits2f(hi >> 16));
}

__device__ __forceinline__ void mma16816(float* d, const uint32_t* a,
                                         const uint32_t* b) {
    asm volatile(
        "mma.sync.aligned.m16n8k16.row.col.f32.bf16.bf16.f32 "
        "{%0,%1,%2,%3}, {%4,%5,%6,%7}, {%8,%9}, {%0,%1,%2,%3};"
        : "+f"(d[0]), "+f"(d[1]), "+f"(d[2]), "+f"(d[3])
        : "r"(a[0]), "r"(a[1]), "r"(a[2]), "r"(a[3]), "r"(b[0]), "r"(b[1]));
}
__device__ __forceinline__ void ldm_x4(uint32_t* r, uint32_t addr) {
    asm volatile("ldmatrix.sync.aligned.m8n8.x4.shared.b16 {%0,%1,%2,%3}, [%4];"
                 : "=r"(r[0]), "=r"(r[1]), "=r"(r[2]), "=r"(r[3]) : "r"(addr));
}
__device__ __forceinline__ void ldm_x2(uint32_t* r, uint32_t addr) {
    asm volatile("ldmatrix.sync.aligned.m8n8.x2.shared.b16 {%0,%1}, [%2];"
                 : "=r"(r[0]), "=r"(r[1]) : "r"(addr));
}
__device__ __forceinline__ void cpa16(uint32_t dst, const void* src) {
    asm volatile("cp.async.cg.shared.global [%0], [%1], 16;" :: "r"(dst), "l"(src));
}
__device__ __forceinline__ void cp_commit() {
    asm volatile("cp.async.commit_group;" ::: "memory");
}
template <int N>
__device__ __forceinline__ void cp_wait() {
    asm volatile("cp.async.wait_group %0;" :: "n"(N) : "memory");
}

// ---------------------------------------------------------------------------
// Pre-convert: fp32 -> (hi, lo) bf16 planes
// ---------------------------------------------------------------------------
__global__ void convert_split_k(const float4* __restrict__ in,
                                uint2* __restrict__ hi, uint2* __restrict__ lo,
                                int n4)
{
    int i = blockIdx.x * blockDim.x + threadIdx.x;
    if (i >= n4) return;
    float4 v = in[i];
    uint32_t h0, l0, h1, l1;
    packsplit(v.x, v.y, h0, l0);
    packsplit(v.z, v.w, h1, l1);
    hi[i] = make_uint2(h0, h1);
    lo[i] = make_uint2(l0, l1);
}

// ---------------------------------------------------------------------------
// bf16 3-term-split GEMM: C[M,N] = A[M,K] @ W[N,K]^T + bias[N]
// CTA tile 128x256, BK=32, 8 warps (2m x 4n), warp tile 64x64.
// 3-stage cp.async ring, ONE barrier per chunk, ldmatrix frags, 80B row stride.
// MODE 0: fp32 C out.  MODE 1: QKV out (Q/K planes + V transposed planes).
// ---------------------------------------------------------------------------
#define GBM 128
#define GBN 256
#define GBK 32
#define GA_LO  10240u
#define GB_HI  20480u
#define GB_LO  40960u
#define GSTAGE 61440u
#define GEMM_SMEM (3u * GSTAGE)   // 184320 bytes

template <int MODE>
__global__ __launch_bounds__(256, 1)
void gemm_bf3(const bf16* __restrict__ Ah, const bf16* __restrict__ Al,
              const bf16* __restrict__ Bh, const bf16* __restrict__ Bl,
              const float* __restrict__ bias, float* __restrict__ C,
              bf16* __restrict__ qkh, bf16* __restrict__ qkl,
              bf16* __restrict__ vth, bf16* __restrict__ vtl,
              int M, int N, int K)
{
    extern __shared__ __align__(16) char sm[];
    const uint32_t sb = smem_u32(sm);
    const int tid = threadIdx.x;
    const int wid = tid >> 5, lane = tid & 31;
    const int g = lane >> 2, tg = lane & 3;
    const int m0 = blockIdx.y * GBM, n0 = blockIdx.x * GBN;
    const int m0w = (wid >> 2) * 64, n0w = (wid & 3) * 64;

    float acc[4][8][4];
#pragma unroll
    for (int i = 0; i < 4; i++)
#pragma unroll
        for (int j = 0; j < 8; j++)
#pragma unroll
            for (int e = 0; e < 4; e++) acc[i][j][e] = 0.0f;

    auto load_stage = [&](int c) {
        const int kt = c * GBK;
        const uint32_t so = (uint32_t)(c % 3) * GSTAGE;
#pragma unroll
        for (int i = 0; i < 4; i++) {                 // A: 1024 16B chunks
            int ci = tid + i * 256;
            int row = ci >> 3, sub = ci & 7;
            int pl = sub >> 2, kc = sub & 3;
            const bf16* src = (pl ? Al : Ah) + (size_t)(m0 + row) * K + kt + kc * 8;
            cpa16(sb + so + (pl ? GA_LO : 0u) + (uint32_t)(row * 80 + kc * 16), src);
        }
#pragma unroll
        for (int i = 0; i < 8; i++) {                 // B: 2048 16B chunks
            int ci = tid + i * 256;
            int row = ci >> 3, sub = ci & 7;
            int pl = sub >> 2, kc = sub & 3;
            const bf16* src = (pl ? Bl : Bh) + (size_t)(n0 + row) * K + kt + kc * 8;
            cpa16(sb + so + (pl ? GB_LO : GB_HI) + (uint32_t)(row * 80 + kc * 16), src);
        }
        cp_commit();
    };

    auto compute = [&](int c) {
        const uint32_t so = (uint32_t)(c % 3) * GSTAGE;
#pragma unroll
        for (int ks = 0; ks < 2; ks++) {
            const uint32_t kb = (uint32_t)(ks * 32);
            uint32_t aH[4][4], aL[4][4];
#pragma unroll
            for (int mf = 0; mf < 4; mf++) {
                uint32_t ad = sb + so +
                    (uint32_t)((m0w + mf * 16 + (lane & 15)) * 80) +
                    kb + (uint32_t)((lane >> 4) * 16);
                ldm_x4(aH[mf], ad);
                ldm_x4(aL[mf], ad + GA_LO);
            }
#pragma unroll
            for (int nf = 0; nf < 8; nf++) {
                uint32_t bd = sb + so + GB_HI +
                    (uint32_t)((n0w + nf * 8 + (lane & 7)) * 80) +
                    kb + (uint32_t)(((lane >> 3) & 1) * 16);
                uint32_t bH[2], bL[2];
                ldm_x2(bH, bd);
                ldm_x2(bL, bd + 20480u);
#pragma unroll
                for (int mf = 0; mf < 4; mf++) {
                    mma16816(acc[mf][nf], aH[mf], bH);
                    mma16816(acc[mf][nf], aH[mf], bL);
                    mma16816(acc[mf][nf], aL[mf], bH);
                }
            }
        }
    };

    const int NC = K / GBK;
    load_stage(0);
    load_stage(1);
    for (int c = 0; c < NC; c++) {
        if (c == NC - 1) cp_wait<0>(); else cp_wait<1>();
        __syncthreads();
        if (c + 2 < NC) load_stage(c + 2);
        compute(c);
    }

    // ---- epilogue ----
#pragma unroll
    for (int mf = 0; mf < 4; mf++) {
        const int r = m0 + m0w + mf * 16 + g;
#pragma unroll
        for (int nf = 0; nf < 8; nf++) {
            const int col = n0 + n0w + nf * 8 + tg * 2;
            const float b0 = bias[col], b1 = bias[col + 1];
#pragma unroll
            for (int half = 0; half < 2; half++) {
                const int rr = r + half * 8;
                const float v0 = acc[mf][nf][half * 2 + 0] + b0;
                const float v1 = acc[mf][nf][half * 2 + 1] + b1;
                if (MODE == 0) {
                    *(float2*)(C + (size_t)rr * N + col) = make_float2(v0, v1);
                } else {
                    if (col < 2048) {
                        uint32_t hi, lo;
                        packsplit(v0, v1, hi, lo);
                        *(uint32_t*)(qkh + (size_t)rr * 2048 + col) = hi;
                        *(uint32_t*)(qkl + (size_t)rr * 2048 + col) = lo;
                    } else {
                        const int d = col - 2048;
                        const int hh = d >> 6, dd = d & 63;
                        const int bb = rr >> 11, rs = rr & 2047;
                        const size_t vb =
                            ((size_t)(bb * NH + hh) * HD + dd) * SEQ + rs;
                        uint32_t h0 = f2bfbits(v0);
                        vth[vb] = *reinterpret_cast<bf16*>(&h0);
                        uint32_t l0 = f2bfbits(v0 - bfbits2f(h0));
                        vtl[vb] = *reinterpret_cast<bf16*>(&l0);
                        uint32_t h1 = f2bfbits(v1);
                        vth[vb + SEQ] = *reinterpret_cast<bf16*>(&h1);
                        uint32_t l1 = f2bfbits(v1 - bfbits2f(h1));
                        vtl[vb + SEQ] = *reinterpret_cast<bf16*>(&l1);
                    }
                }
            }
        }
    }
}

// ---------------------------------------------------------------------------
// Flash attention, bf16 3-term split, double-buffered KV via cp.async.
// CTA = 128 q rows x (b,h); 8 warps x 16 q rows; KV tiles of 128.
// smem: Q planes (36.9KB) + 2 KV stages (70KB each) = 176KB.
// ---------------------------------------------------------------------------
#define AQ_LO   18432u
#define AKV0    36864u
#define AKV_KLO 18432u   // within stage
#define AKV_VHI 36864u
#define AKV_VLO 54272u
#define AKVSTG  71680u
#define ATT_SMEM (AKV0 + 2u * AKVSTG)   // 180224 bytes

__global__ __launch_bounds__(256, 1)
void attention_mma(const bf16* __restrict__ qkh, const bf16* __restrict__ qkl,
                   const bf16* __restrict__ vth, const bf16* __restrict__ vtl,
                   bf16* __restrict__ ath, bf16* __restrict__ atl,
                   const int* __restrict__ causal_flag)
{
    extern __shared__ __align__(16) char sm[];
    const uint32_t sb = smem_u32(sm);
    const int tid = threadIdx.x, wid = tid >> 5, lane = tid & 31;
    const int g = lane >> 2, tg = lane & 3;
    const int qt = (SEQ / 128 - 1) - blockIdx.x;   // long CTAs first
    const int bh = blockIdx.y, b = bh / NH, h = bh % NH;
    const int causal = *causal_flag;
    const int q0 = qt * 128;

    auto load_kv = [&](int kvt, int st) {
        const int kv0 = kvt * 128;
        const uint32_t so = AKV0 + (uint32_t)st * AKVSTG;
#pragma unroll
        for (int i = 0; i < 8; i++) {            // K: 2048 chunks
            int ci = tid + i * 256;
            int row = ci >> 4, sub = ci & 15;
            int pl = sub >> 3, kc = sub & 7;
            const bf16* src = (pl ? qkl : qkh) +
                (size_t)(b * SEQ + kv0 + row) * 2048 + 1024 + h * HD + kc * 8;
            cpa16(sb + so + (pl ? AKV_KLO : 0u) + (uint32_t)(row * 144 + kc * 16), src);
        }
#pragma unroll
        for (int i = 0; i < 8; i++) {            // V: 2048 chunks
            int ci = tid + i * 256;
            int pl = ci >> 10, rem = ci & 1023;
            int row = rem >> 4, kc = rem & 15;
            const bf16* src = (pl ? vtl : vth) +
                ((size_t)bh * HD + row) * SEQ + kv0 + kc * 8;
            cpa16(sb + so + (pl ? AKV_VLO : AKV_VHI) + (uint32_t)(row * 272 + kc * 16), src);
        }
        cp_commit();
    };

    // ---- prologue: Q tile + KV(0), one group ----
#pragma unroll
    for (int i = 0; i < 8; i++) {
        int ci = tid + i * 256;
        int row = ci >> 4, sub = ci & 15;
        int pl = sub >> 3, kc = sub & 7;
        const bf16* src = (pl ? qkl : qkh) +
            (size_t)(b * SEQ + q0 + row) * 2048 + h * HD + kc * 8;
        cpa16(sb + (pl ? AQ_LO : 0u) + (uint32_t)(row * 144 + kc * 16), src);
    }
    load_kv(0, 0);

    float o[8][4];
#pragma unroll
    for (int i = 0; i < 8; i++)
#pragma unroll
        for (int e = 0; e < 4; e++) o[i][e] = 0.0f;
    float m0v = -1e30f, m1v = -1e30f, l0v = 0.0f, l1v = 0.0f;

    const int nkv = causal ? (qt + 1) : (SEQ / 128);
    for (int kvt = 0; kvt < nkv; kvt++) {
        cp_wait<0>();
        __syncthreads();
        if (kvt + 1 < nkv) load_kv(kvt + 1, (kvt + 1) & 1);  // overlaps compute

        const uint32_t kvb = AKV0 + (uint32_t)(kvt & 1) * AKVSTG;

        // ---- S = Q @ K^T ----
        float s[16][4];
#pragma unroll
        for (int nf = 0; nf < 16; nf++)
#pragma unroll
            for (int e = 0; e < 4; e++) s[nf][e] = 0.0f;

#pragma unroll
        for (int ks = 0; ks < 4; ks++) {
            const uint32_t kb = (uint32_t)(ks * 32);
            uint32_t aH[4], aL[4];
            uint32_t ad = sb + (uint32_t)((wid * 16 + (lane & 15)) * 144) +
                          kb + (uint32_t)((lane >> 4) * 16);
            ldm_x4(aH, ad);
            ldm_x4(aL, ad + AQ_LO);
#pragma unroll
            for (int nf = 0; nf < 16; nf++) {
                uint32_t bd = sb + kvb +
                    (uint32_t)((nf * 8 + (lane & 7)) * 144) +
                    kb + (uint32_t)(((lane >> 3) & 1) * 16);
                uint32_t bH[2], bL[2];
                ldm_x2(bH, bd);
                ldm_x2(bL, bd + AKV_KLO);
                mma16816(s[nf], aH, bH);
                mma16816(s[nf], aH, bL);
                mma16816(s[nf], aL, bH);
            }
        }

        // ---- scale + causal mask (diagonal tile only) ----
        const bool dm = (causal != 0) && (kvt == qt);
#pragma unroll
        for (int nf = 0; nf < 16; nf++) {
#pragma unroll
            for (int e = 0; e < 4; e++) {
                float v = s[nf][e] * 0.125f;   // 1/sqrt(64)
                if (dm) {
                    int qr = wid * 16 + g + ((e >= 2) ? 8 : 0);
                    int kc = nf * 8 + tg * 2 + (e & 1);
                    if (kc > qr) v = -1e30f;
                }
                s[nf][e] = v;
            }
        }

        // ---- online softmax (rows g and g+8) ----
        float mx0 = -1e30f, mx1 = -1e30f;
#pragma unroll
        for (int nf = 0; nf < 16; nf++) {
            mx0 = fmaxf(mx0, fmaxf(s[nf][0], s[nf][1]));
            mx1 = fmaxf(mx1, fmaxf(s[nf][2], s[nf][3]));
        }
        mx0 = fmaxf(mx0, __shfl_xor_sync(0xffffffffu, mx0, 1));
        mx0 = fmaxf(mx0, __shfl_xor_sync(0xffffffffu, mx0, 2));
        mx1 = fmaxf(mx1, __shfl_xor_sync(0xffffffffu, mx1, 1));
        mx1 = fmaxf(mx1, __shfl_xor_sync(0xffffffffu, mx1, 2));

        const float mn0 = fmaxf(m0v, mx0), mn1 = fmaxf(m1v, mx1);
        const float al0 = __expf(m0v - mn0), al1 = __expf(m1v - mn1);
        m0v = mn0; m1v = mn1;

        float rs0 = 0.0f, rs1 = 0.0f;
#pragma unroll
        for (int nf = 0; nf < 16; nf++) {
            s[nf][0] = __expf(s[nf][0] - mn0); rs0 += s[nf][0];
            s[nf][1] = __expf(s[nf][1] - mn0); rs0 += s[nf][1];
            s[nf][2] = __expf(s[nf][2] - mn1); rs1 += s[nf][2];
            s[nf][3] = __expf(s[nf][3] - mn1); rs1 += s[nf][3];
        }
        rs0 += __shfl_xor_sync(0xffffffffu, rs0, 1);
        rs0 += __shfl_xor_sync(0xffffffffu, rs0, 2);
        rs1 += __shfl_xor_sync(0xffffffffu, rs1, 1);
        rs1 += __shfl_xor_sync(0xffffffffu, rs1, 2);
        l0v = l0v * al0 + rs0;
        l1v = l1v * al1 + rs1;

#pragma unroll
        for (int nf = 0; nf < 8; nf++) {
            o[nf][0] *= al0; o[nf][1] *= al0;
            o[nf][2] *= al1; o[nf][3] *= al1;
        }

        // ---- O += P @ V (P split from registers; V^T frags via ldmatrix) ----
#pragma unroll
        for (int kf = 0; kf < 8; kf++) {
            uint32_t aH[4], aL[4];
            packsplit(s[2 * kf][0],     s[2 * kf][1],     aH[0], aL[0]);
            packsplit(s[2 * kf][2],     s[2 * kf][3],     aH[1], aL[1]);
            packsplit(s[2 * kf + 1][0], s[2 * kf + 1][1], aH[2], aL[2]);
            packsplit(s[2 * kf + 1][2], s[2 * kf + 1][3], aH[3], aL[3]);
#pragma unroll
            for (int nf = 0; nf < 8; nf++) {
                uint32_t vd = sb + kvb + AKV_VHI +
                    (uint32_t)((nf * 8 + (lane & 7)) * 272) +
                    (uint32_t)(kf * 32) + (uint32_t)(((lane >> 3) & 1) * 16);
                uint32_t bH[2], bL[2];
                ldm_x2(bH, vd);
                ldm_x2(bL, vd + 17408u);
                mma16816(o[nf], aH, bH);
                mma16816(o[nf], aH, bL);
                mma16816(o[nf], aL, bH);
            }
        }
        __syncthreads();   // all warps done with stage before next overwrite
    }

    // ---- normalize + write hi/lo planes of O ----
    const float inv0 = 1.0f / l0v, inv1 = 1.0f / l1v;
    const size_t r0 = (size_t)(b * SEQ + q0 + wid * 16 + g);
#pragma unroll
    for (int nf = 0; nf < 8; nf++) {
        const int col = h * HD + nf * 8 + tg * 2;
        uint32_t hi, lo;
        packsplit(o[nf][0] * inv0, o[nf][1] * inv0, hi, lo);
        *(uint32_t*)(ath + r0 * EMB + col) = hi;
        *(uint32_t*)(atl + r0 * EMB + col) = lo;
        packsplit(o[nf][2] * inv1, o[nf][3] * inv1, hi, lo);
        *(uint32_t*)(ath + (r0 + 8) * EMB + col) = hi;
        *(uint32_t*)(atl + (r0 + 8) * EMB + col) = lo;
    }
}

// ---------------------------------------------------------------------------
extern "C" void kernel_launch(void* const* d_in, const int* in_sizes, int n_in,
                              void* d_out, int out_size)
{
    (void)in_sizes; (void)n_in; (void)out_size;
    const float* x      = (const float*)d_in[0];
    const float* w_qkv  = (const float*)d_in[1];
    const float* b_qkv  = (const float*)d_in[2];
    const float* w_out  = (const float*)d_in[3];
    const float* b_out  = (const float*)d_in[4];
    const int*   causal = (const int*)d_in[5];
    float* out = (float*)d_out;

    bf16 *xh, *xl, *wqh, *wql, *woh, *wol, *qkh, *qkl, *vth, *vtl, *ath, *atl;
    cudaGetSymbolAddress((void**)&xh,  g_xh);   cudaGetSymbolAddress((void**)&xl,  g_xl);
    cudaGetSymbolAddress((void**)&wqh, g_wqh);  cudaGetSymbolAddress((void**)&wql, g_wql);
    cudaGetSymbolAddress((void**)&woh, g_woh);  cudaGetSymbolAddress((void**)&wol, g_wol);
    cudaGetSymbolAddress((void**)&qkh, g_qkh);  cudaGetSymbolAddress((void**)&qkl, g_qkl);
    cudaGetSymbolAddress((void**)&vth, g_vth);  cudaGetSymbolAddress((void**)&vtl, g_vtl);
    cudaGetSymbolAddress((void**)&ath, g_ath);  cudaGetSymbolAddress((void**)&atl, g_atl);

    cudaFuncSetAttribute(gemm_bf3<0>, cudaFuncAttributeMaxDynamicSharedMemorySize,
                         (int)GEMM_SMEM);
    cudaFuncSetAttribute(gemm_bf3<1>, cudaFuncAttributeMaxDynamicSharedMemorySize,
                         (int)GEMM_SMEM);
    cudaFuncSetAttribute(attention_mma, cudaFuncAttributeMaxDynamicSharedMemorySize,
                         (int)ATT_SMEM);

    // 1) pre-convert inputs to bf16 hi/lo planes
    convert_split_k<<<(MTOT * EMB / 4 + 255) / 256, 256>>>(
        (const float4*)x, (uint2*)xh, (uint2*)xl, MTOT * EMB / 4);
    convert_split_k<<<(NQKV * EMB / 4 + 255) / 256, 256>>>(
        (const float4*)w_qkv, (uint2*)wqh, (uint2*)wql, NQKV * EMB / 4);
    convert_split_k<<<(EMB * EMB / 4 + 255) / 256, 256>>>(
        (const float4*)w_out, (uint2*)woh, (uint2*)wol, EMB * EMB / 4);

    // 2) QKV projection -> Q/K planes + transposed V planes
    gemm_bf3<1><<<dim3(NQKV / GBN, MTOT / GBM), 256, GEMM_SMEM>>>(
        xh, xl, wqh, wql, b_qkv, nullptr, qkh, qkl, vth, vtl, MTOT, NQKV, EMB);

    // 3) causal flash attention -> O hi/lo planes
    attention_mma<<<dim3(SEQ / 128, BATCH * NH), 256, ATT_SMEM>>>(
        qkh, qkl, vth, vtl, ath, atl, causal);

    // 4) output projection -> fp32 out
    gemm_bf3<0><<<dim3(EMB / GBN, MTOT / GBM), 256, GEMM_SMEM>>>(
        ath, atl, woh, wol, b_out, out, nullptr, nullptr, nullptr, nullptr,
        MTOT, EMB, EMB);
}